// round 2
// baseline (speedup 1.0000x reference)
#include <cuda_runtime.h>
#include <cuda_bf16.h>

// Problem constants
#define BB 2
#define NN 16384
#define CIN 64
#define SS 4096
#define NSAMP 32

// Output layout (floats): new_xyz | new_features | scores
#define OUT_XYZ_OFF   0
#define OUT_FEAT_OFF  (BB * SS * 3)                       // 24576
#define OUT_SCORE_OFF (OUT_FEAT_OFF + BB * 128 * SS)      // 1073152

// ---------------- scratch (no allocations allowed) ----------------
__device__ float g_featsT[BB * NN * CIN];    // (B,N,C) transposed features, 8 MB
__device__ int   g_ballIdx[BB * SS * NSAMP]; // neighbor indices
__device__ int   g_ballCnt[BB * SS];         // in-ball counts (0 => empty)

// ---------------- packed f32x2 helpers (exact per-lane RN) ----------------
#define F32X2_ADD(d, a, b) asm("add.rn.f32x2 %0, %1, %2;" : "=l"(d) : "l"(a), "l"(b))
#define F32X2_MUL(d, a, b) asm("mul.rn.f32x2 %0, %1, %2;" : "=l"(d) : "l"(a), "l"(b))
#define PACK2(d, lo, hi)   asm("mov.b64 %0, {%1, %2};" : "=l"(d) : "f"(lo), "f"(hi))
#define UNPACK2(lo, hi, s) asm("mov.b64 {%0, %1}, %2;" : "=f"(lo), "=f"(hi) : "l"(s))

// =================================================================
// Kernel 1: farthest point sampling (one block per batch)
//  - x,y in registers (f32x2 packed pairs); z + dist pairs in smem float4
//  - packed add/mul.rn.f32x2 distance (bit-identical to scalar RN)
//  - lazy per-thread argmax (rescan only when this thread updated a dist)
//  - u64-key reduction: (dist_bits << 14) | (16383 - i)  -> exact
//    argmax with first-index tie-break; winner's x,y carried via shuffles
// =================================================================
#define FPS_T 1024
#define FPS_PAIRS 8   // 16 points per thread, as 8 packed pairs

__global__ __launch_bounds__(FPS_T) void fps_kernel(
    const float* __restrict__ xyz, float* __restrict__ out_newxyz)
{
    extern __shared__ float4 s_zd[];   // [8][1024] : (z0, z1, dist0, dist1) per pair
    __shared__ unsigned long long s_key[32];
    __shared__ float s_kx[32], s_ky[32];
    __shared__ int   s_far;
    __shared__ float s_fx, s_fy;

    const int b    = blockIdx.x;
    const int tid  = threadIdx.x;
    const int lane = tid & 31, wid = tid >> 5;
    const float* xb = xyz + (size_t)b * NN * 3;

    // point mapping: pair p of thread tid owns points i0 = p*2048 + 2*tid, i0+1
    unsigned long long PX[FPS_PAIRS], PY[FPS_PAIRS];
#pragma unroll
    for (int p = 0; p < FPS_PAIRS; p++) {
        const int i0 = p * 2048 + (tid << 1);
        const float x0 = xb[3 * i0 + 0], y0 = xb[3 * i0 + 1], z0 = xb[3 * i0 + 2];
        const float x1 = xb[3 * i0 + 3], y1 = xb[3 * i0 + 4], z1 = xb[3 * i0 + 5];
        PACK2(PX[p], x0, x1);
        PACK2(PY[p], y0, y1);
        s_zd[p * 1024 + tid] = make_float4(z0, z1, 1e10f, 1e10f);
    }
    __syncthreads();

    float* outx = out_newxyz + (size_t)b * SS * 3;

    // centroid 0 = original point 0
    float ccx = __ldg(xb + 0), ccy = __ldg(xb + 1), ccz = __ldg(xb + 2);

    // per-thread cached argmax state
    float lmax = -1.0f, lx = 0.f, ly = 0.f;
    int   lmaxi = 0;

    const float* zview = (const float*)s_zd;

    for (int j = 0; j < SS; j++) {
        if (tid == 0) {
            outx[3 * j + 0] = ccx;
            outx[3 * j + 1] = ccy;
            outx[3 * j + 2] = ccz;
        }

        // packed negated centroid (x + (-c) == x - c exactly)
        unsigned long long NCX, NCY, NCZ;
        {
            const float nx = -ccx, ny = -ccy, nz = -ccz;
            PACK2(NCX, nx, nx);
            PACK2(NCY, ny, ny);
            PACK2(NCZ, nz, nz);
        }

        bool dirty = false;
#pragma unroll
        for (int p = 0; p < FPS_PAIRS; p++) {
            float4 zd = s_zd[p * 1024 + tid];          // (z0, z1, d0_old, d1_old)
            unsigned long long pz, dx, dy, dz, s;
            PACK2(pz, zd.x, zd.y);
            F32X2_ADD(dx, PX[p], NCX);
            F32X2_ADD(dy, PY[p], NCY);
            F32X2_ADD(dz, pz,    NCZ);
            F32X2_MUL(dx, dx, dx);
            F32X2_MUL(dy, dy, dy);
            F32X2_MUL(dz, dz, dz);
            F32X2_ADD(s, dx, dy);
            F32X2_ADD(s, s, dz);
            float d0, d1;
            UNPACK2(d0, d1, s);
            const bool u0 = d0 < zd.z;
            const bool u1 = d1 < zd.w;
            if (u0 | u1) {
                const float nd0 = u0 ? d0 : zd.z;
                const float nd1 = u1 ? d1 : zd.w;
                *(float2*)((float*)&s_zd[p * 1024 + tid] + 2) = make_float2(nd0, nd1);
                dirty = true;
            }
        }

        if (dirty) {
            lmax = -1.0f; lmaxi = 0; lx = 0.f; ly = 0.f;
#pragma unroll
            for (int p = 0; p < FPS_PAIRS; p++) {
                const float4 zd = s_zd[p * 1024 + tid];
                float x0, x1, y0, y1;
                UNPACK2(x0, x1, PX[p]);
                UNPACK2(y0, y1, PY[p]);
                const int i0 = p * 2048 + (tid << 1);
                if (zd.z > lmax) { lmax = zd.z; lmaxi = i0;     lx = x0; ly = y0; }
                if (zd.w > lmax) { lmax = zd.w; lmaxi = i0 + 1; lx = x1; ly = y1; }
            }
        }

        // warp reduce: key = (bits(lmax) << 14) | (16383 - i)  (max => first-index argmax)
        unsigned long long key =
            ((unsigned long long)__float_as_uint(lmax) << 14) |
            (unsigned long long)(16383 - lmaxi);
        float kx = lx, ky = ly;
#pragma unroll
        for (int off = 16; off; off >>= 1) {
            const unsigned long long ok = __shfl_down_sync(0xffffffffu, key, off);
            const float ox = __shfl_down_sync(0xffffffffu, kx, off);
            const float oy = __shfl_down_sync(0xffffffffu, ky, off);
            if (ok > key) { key = ok; kx = ox; ky = oy; }
        }
        if (lane == 0) { s_key[wid] = key; s_kx[wid] = kx; s_ky[wid] = ky; }
        __syncthreads();
        if (wid == 0) {
            key = s_key[lane]; kx = s_kx[lane]; ky = s_ky[lane];
#pragma unroll
            for (int off = 16; off; off >>= 1) {
                const unsigned long long ok = __shfl_down_sync(0xffffffffu, key, off);
                const float ox = __shfl_down_sync(0xffffffffu, kx, off);
                const float oy = __shfl_down_sync(0xffffffffu, ky, off);
                if (ok > key) { key = ok; kx = ox; ky = oy; }
            }
            if (lane == 0) {
                s_far = 16383 - (int)(key & 0x3FFFull);
                s_fx = kx; s_fy = ky;
            }
        }
        __syncthreads();
        const int far = s_far;
        ccx = s_fx; ccy = s_fy;
        // z of winner from smem (broadcast LDS)
        const int fp = far >> 11;           // pair block
        const int ft = (far >> 1) & 1023;   // owner thread
        ccz = zview[(fp * 1024 + ft) * 4 + (far & 1)];
    }
}

// =================================================================
// Kernel 2: transpose features (B,C,N) -> (B,N,C)
// =================================================================
__global__ void transpose_kernel(const float* __restrict__ f)
{
    __shared__ float tile[32][33];
    const int b  = blockIdx.z;
    const int n0 = blockIdx.x * 32;
    const int c0 = blockIdx.y * 32;
    const int tx = threadIdx.x, ty = threadIdx.y;
    tile[ty][tx] = f[((size_t)b * CIN + (c0 + ty)) * NN + n0 + tx];
    __syncthreads();
    g_featsT[((size_t)b * NN + (n0 + ty)) * CIN + c0 + tx] = tile[tx][ty];
}

// =================================================================
// Kernel 3: ball query (one warp per group), first-32-ascending
// =================================================================
__global__ void ballq_kernel(const float* __restrict__ xyz,
                             const float* __restrict__ newxyz)
{
    const int g    = blockIdx.x * 8 + (threadIdx.x >> 5);
    const int lane = threadIdx.x & 31;
    const int b    = g >> 12;
    const float* xb = xyz + (size_t)b * NN * 3;

    const float cx = newxyz[g * 3 + 0];
    const float cy = newxyz[g * 3 + 1];
    const float cz = newxyz[g * 3 + 2];

    int* out = g_ballIdx + g * NSAMP;
    int cnt = 0;

    for (int base = 0; base < NN && cnt < NSAMP; base += 32) {
        const int i = base + lane;
        const float dx = xb[3 * i + 0] - cx;
        const float dy = xb[3 * i + 1] - cy;
        const float dz = xb[3 * i + 2] - cz;
        const float d2 = __fadd_rn(__fadd_rn(__fmul_rn(dx, dx), __fmul_rn(dy, dy)),
                                   __fmul_rn(dz, dz));
        const bool inb = d2 < 0.25f;  // radius^2 = 0.25 exactly
        const unsigned m = __ballot_sync(0xffffffffu, inb);
        const int pos = cnt + __popc(m & ((1u << lane) - 1u));
        if (inb && pos < NSAMP) out[pos] = i;
        cnt += __popc(m);
    }
    __syncwarp();
    if (cnt == 0) {
        out[lane] = 0;
    } else if (cnt < NSAMP) {
        const int first = out[0];
        if (lane >= cnt) out[lane] = first;
    }
    if (lane == 0) g_ballCnt[g] = cnt;
}

// =================================================================
// Kernel 4: fused gather + 3-layer MLP + maxpool + agg + score
// One block (256 threads) per group. Weight smem strides padded to
// odd (65/65/129) => conflict-free staging stores AND compute loads.
// =================================================================
#define W1_STR 65
#define W2_STR 65
#define W3_STR 129
#define SM_INT_F   (67 * 36)          // 2412 (div by 4)
#define SM_W1_F    4356               // 67*65 padded to mult of 4
#define SM_W2_F    (64 * W2_STR)      // 4160
#define SM_W3_F    (64 * W3_STR + 0)  // 8256
#define SM_H_F     (64 * 36)          // 2304
#define MLP_SMEM_FLOATS (SM_INT_F + SM_W1_F + SM_W2_F + SM_W3_F + 2 * SM_H_F + 256 + 256 + 128 + 128 + 32)

__global__ __launch_bounds__(256, 2) void group_mlp_kernel(
    const float* __restrict__ xyz,
    const float* __restrict__ newxyz,
    const float* __restrict__ w1, const float* __restrict__ b1,
    const float* __restrict__ w2, const float* __restrict__ b2,
    const float* __restrict__ w3, const float* __restrict__ b3,
    const float* __restrict__ wa, const float* __restrict__ ba,
    const float* __restrict__ wc, const float* __restrict__ bc,
    float* __restrict__ d_out)
{
    extern __shared__ float sm[];
    float* inT     = sm;                    // [67][36]  input  (i-major, nb fast)
    float* w1s     = inT + SM_INT_F;        // [67][65]  (i-major, oc fast, padded)
    float* w2s     = w1s + SM_W1_F;         // [64][65]
    float* w3s     = w2s + SM_W2_F;         // [64][129]
    float* h1T     = w3s + SM_W3_F;         // [64][36]
    float* h2T     = h1T + SM_H_F;          // [64][36]
    float* bss     = h2T + SM_H_F;          // b1[64] b2[64] b3[128]
    float* poolbuf = bss + 256;             // [128][2]
    float* pooled  = poolbuf + 256;         // [128]
    float* aggv    = pooled + 128;          // [128]
    int*   idxs    = (int*)(aggv + 128);    // [32]

    const int g = blockIdx.x;
    const int b = g >> 12;
    const int s = g & 4095;
    const int tid = threadIdx.x;

    // ---- stage indices, biases, weights (transposed, padded strides) ----
    if (tid < 32)  idxs[tid] = g_ballIdx[g * NSAMP + tid];
    if (tid < 64)       bss[tid] = b1[tid];
    else if (tid < 128) bss[tid] = b2[tid - 64];
    if (tid < 128) bss[128 + tid] = b3[tid];

    for (int e = tid; e < 64 * 67; e += 256) {
        const int oc = e / 67, i = e % 67;
        w1s[i * W1_STR + oc] = w1[e];
    }
    for (int e = tid; e < 64 * 64; e += 256) {
        const int oc = e >> 6, i = e & 63;
        w2s[i * W2_STR + oc] = w2[e];
    }
    for (int e = tid; e < 128 * 64; e += 256) {
        const int oc = e >> 6, i = e & 63;
        w3s[i * W3_STR + oc] = w3[e];
    }
    __syncthreads();

    // ---- gather: inT[i][nb] = (i<3) ? xyz[idx]-center : featsT[idx][i-3] ----
    const float* xb = xyz + (size_t)b * NN * 3;
    const float cx = newxyz[g * 3 + 0];
    const float cy = newxyz[g * 3 + 1];
    const float cz = newxyz[g * 3 + 2];
    for (int e = tid; e < 32 * 67; e += 256) {
        const int nb = e & 31;
        const int i  = e >> 5;
        const int pi = idxs[nb];
        float v;
        if (i == 0)      v = xb[pi * 3 + 0] - cx;
        else if (i == 1) v = xb[pi * 3 + 1] - cy;
        else if (i == 2) v = xb[pi * 3 + 2] - cz;
        else             v = g_featsT[((size_t)b * NN + pi) * CIN + (i - 3)];
        inT[i * 36 + nb] = v;
    }
    __syncthreads();

    // ---- layer 1: 67 -> 64, ReLU ----
    {
        const int oc = tid & 63, ng = tid >> 6;  // 4 groups of 8 neighbors
        float acc[8];
        const float bv = bss[oc];
#pragma unroll
        for (int n = 0; n < 8; n++) acc[n] = bv;
        for (int i = 0; i < 67; i++) {
            const float w = w1s[i * W1_STR + oc];
            const float4* xp = (const float4*)(inT + i * 36 + ng * 8);
            const float4 x0 = xp[0], x1 = xp[1];
            acc[0] += w * x0.x; acc[1] += w * x0.y; acc[2] += w * x0.z; acc[3] += w * x0.w;
            acc[4] += w * x1.x; acc[5] += w * x1.y; acc[6] += w * x1.z; acc[7] += w * x1.w;
        }
        float* hp = h1T + oc * 36 + ng * 8;
#pragma unroll
        for (int n = 0; n < 8; n++) hp[n] = fmaxf(acc[n], 0.f);
    }
    __syncthreads();

    // ---- layer 2: 64 -> 64, ReLU ----
    {
        const int oc = tid & 63, ng = tid >> 6;
        float acc[8];
        const float bv = bss[64 + oc];
#pragma unroll
        for (int n = 0; n < 8; n++) acc[n] = bv;
        for (int i = 0; i < 64; i++) {
            const float w = w2s[i * W2_STR + oc];
            const float4* xp = (const float4*)(h1T + i * 36 + ng * 8);
            const float4 x0 = xp[0], x1 = xp[1];
            acc[0] += w * x0.x; acc[1] += w * x0.y; acc[2] += w * x0.z; acc[3] += w * x0.w;
            acc[4] += w * x1.x; acc[5] += w * x1.y; acc[6] += w * x1.z; acc[7] += w * x1.w;
        }
        float* hp = h2T + oc * 36 + ng * 8;
#pragma unroll
        for (int n = 0; n < 8; n++) hp[n] = fmaxf(acc[n], 0.f);
    }
    __syncthreads();

    // ---- layer 3: 64 -> 128, ReLU fused with local max over neighbors ----
    {
        const int oc = tid & 127, ng = tid >> 7;  // 2 groups of 16 neighbors
        float acc[16];
        const float bv = bss[128 + oc];
#pragma unroll
        for (int n = 0; n < 16; n++) acc[n] = bv;
        for (int i = 0; i < 64; i++) {
            const float w = w3s[i * W3_STR + oc];
            const float4* xp = (const float4*)(h2T + i * 36 + ng * 16);
            const float4 x0 = xp[0], x1 = xp[1], x2 = xp[2], x3 = xp[3];
            acc[0]  += w * x0.x; acc[1]  += w * x0.y; acc[2]  += w * x0.z; acc[3]  += w * x0.w;
            acc[4]  += w * x1.x; acc[5]  += w * x1.y; acc[6]  += w * x1.z; acc[7]  += w * x1.w;
            acc[8]  += w * x2.x; acc[9]  += w * x2.y; acc[10] += w * x2.z; acc[11] += w * x2.w;
            acc[12] += w * x3.x; acc[13] += w * x3.y; acc[14] += w * x3.z; acc[15] += w * x3.w;
        }
        float m = acc[0];
#pragma unroll
        for (int n = 1; n < 16; n++) m = fmaxf(m, acc[n]);
        m = fmaxf(m, 0.f);  // max(relu(x)) == relu(max(x))
        poolbuf[oc * 2 + ng] = m;
    }
    __syncthreads();

    const int cnt = g_ballCnt[g];
    if (tid < 128) {
        const float m = fmaxf(poolbuf[tid * 2], poolbuf[tid * 2 + 1]);
        pooled[tid] = (cnt > 0) ? m : 0.f;
    }
    __syncthreads();

    // ---- aggregation MLP: 128 -> 128, ReLU; write new_features ----
    if (tid < 128) {
        const int o = tid;
        float acc = ba[o];
        const float4* w4 = (const float4*)(wa + o * 128);
#pragma unroll 8
        for (int i = 0; i < 32; i++) {
            const float4 wv = __ldg(w4 + i);
            acc += pooled[4 * i + 0] * wv.x;
            acc += pooled[4 * i + 1] * wv.y;
            acc += pooled[4 * i + 2] * wv.z;
            acc += pooled[4 * i + 3] * wv.w;
        }
        const float a = fmaxf(acc, 0.f);
        aggv[o] = a;
        d_out[OUT_FEAT_OFF + ((size_t)(b * 128 + o)) * SS + s] = a;
    }
    __syncthreads();

    // ---- confidence score: wc . agg + bc ----
    if (tid < 32) {
        float p = 0.f;
#pragma unroll
        for (int k = 0; k < 4; k++) {
            const int i = k * 32 + tid;
            p += aggv[i] * wc[i];
        }
#pragma unroll
        for (int off = 16; off; off >>= 1)
            p += __shfl_down_sync(0xffffffffu, p, off);
        if (tid == 0)
            d_out[OUT_SCORE_OFF + b * SS + s] = p + bc[0];
    }
}

// =================================================================
// launch
// =================================================================
extern "C" void kernel_launch(void* const* d_in, const int* in_sizes, int n_in,
                              void* d_out, int out_size)
{
    const float* xyz      = (const float*)d_in[0];
    const float* features = (const float*)d_in[1];
    const float* w1 = (const float*)d_in[2];
    const float* b1 = (const float*)d_in[3];
    const float* w2 = (const float*)d_in[4];
    const float* b2 = (const float*)d_in[5];
    const float* w3 = (const float*)d_in[6];
    const float* b3 = (const float*)d_in[7];
    const float* wa = (const float*)d_in[8];
    const float* ba = (const float*)d_in[9];
    const float* wc = (const float*)d_in[10];
    const float* bc = (const float*)d_in[11];
    float* out = (float*)d_out;

    static bool attr_set = false;
    if (!attr_set) {
        cudaFuncSetAttribute(fps_kernel, cudaFuncAttributeMaxDynamicSharedMemorySize,
                             FPS_PAIRS * 1024 * (int)sizeof(float4));
        cudaFuncSetAttribute(group_mlp_kernel, cudaFuncAttributeMaxDynamicSharedMemorySize,
                             MLP_SMEM_FLOATS * (int)sizeof(float));
        attr_set = true;
    }

    // 1) FPS -> writes new_xyz into d_out[0:24576)
    fps_kernel<<<BB, FPS_T, FPS_PAIRS * 1024 * sizeof(float4)>>>(xyz, out + OUT_XYZ_OFF);

    // 2) transpose features to (B,N,C)
    transpose_kernel<<<dim3(NN / 32, CIN / 32, BB), dim3(32, 32)>>>(features);

    // 3) ball query
    ballq_kernel<<<(BB * SS) / 8, 256>>>(xyz, out + OUT_XYZ_OFF);

    // 4) fused gather + MLP + pool + agg + score
    group_mlp_kernel<<<BB * SS, 256, MLP_SMEM_FLOATS * sizeof(float)>>>(
        xyz, out + OUT_XYZ_OFF,
        w1, b1, w2, b2, w3, b3, wa, ba, wc, bc, out);
}

// round 3
// speedup vs baseline: 1.0548x; 1.0548x over previous
#include <cuda_runtime.h>
#include <cuda_bf16.h>

// Problem constants
#define BB 2
#define NN 16384
#define CIN 64
#define SS 4096
#define NSAMP 32

// Output layout (floats): new_xyz | new_features | scores
#define OUT_XYZ_OFF   0
#define OUT_FEAT_OFF  (BB * SS * 3)                       // 24576
#define OUT_SCORE_OFF (OUT_FEAT_OFF + BB * 128 * SS)      // 1073152

// ---------------- scratch (no allocations allowed) ----------------
__device__ float g_featsT[BB * NN * CIN];    // (B,N,C) transposed features, 8 MB
__device__ int   g_ballIdx[BB * SS * NSAMP]; // neighbor indices
__device__ int   g_ballCnt[BB * SS];         // in-ball counts (0 => empty)

// =================================================================
// Kernel 1: FPS with spatial-chunk pruning (one 512-thread block per batch)
//  - Morton sort (2048 cells) into 128 chunks x 128 points, AABB per chunk
//  - per iter: chunk rescanned only if dmin2(centroid, AABB) < chunkMax
//    (RN arithmetic is monotone => pruning is exactly lossless)
//  - per-point math bit-identical to reference: ((dx^2+dy^2)+dz^2) RN, fminf
//  - global argmax via u64 key (dist_bits<<14)|(16383-origIdx): exact
//    first-index tie-break, independent of sort permutation
// =================================================================
#define FPS_T   512
#define FPS_W   16     // warps
#define NCH     128    // chunks
#define CHQ     8      // chunks per warp
#define NCELL   2048

// dynamic smem bytes:
//   float2 sxy[16384]      : 131072
//   u32    perm[16384]     :  65536
//   u32    hist[2048]      :   8192
//   float  aabb[128*6]     :   3072
//   u64    ckey[128]       :   1024
//   float  cbx/cby/cbz[128]:   1536
#define FPS_SMEM_BYTES (131072 + 65536 + 8192 + 3072 + 1024 + 1536)

__device__ __forceinline__ int fps_cell(float x, float y, float z,
                                        float mnx, float mny, float mnz,
                                        float isx, float isy, float isz)
{
    int qx = __float2int_rd((x - mnx) * isx); qx = max(0, min(15, qx));
    int qy = __float2int_rd((y - mny) * isy); qy = max(0, min(15, qy));
    int qz = __float2int_rd((z - mnz) * isz); qz = max(0, min(7,  qz));
    return  (qx & 1)        | ((qy & 1) << 1)        | ((qz & 1) << 2)
         | (((qx >> 1) & 1) << 3) | (((qy >> 1) & 1) << 4) | (((qz >> 1) & 1) << 5)
         | (((qx >> 2) & 1) << 6) | (((qy >> 2) & 1) << 7) | (((qz >> 2) & 1) << 8)
         | (((qx >> 3) & 1) << 9) | (((qy >> 3) & 1) << 10);
}

__global__ __launch_bounds__(FPS_T) void fps_kernel(
    const float* __restrict__ xyz, float* __restrict__ out_newxyz)
{
    extern __shared__ unsigned char fraw[];
    float2*   sxy  = (float2*)fraw;                       // [16384]
    unsigned* perm = (unsigned*)(sxy + NN);               // [16384]
    unsigned* hist = perm + NN;                           // [2048]
    float*    aabb = (float*)(hist + NCELL);              // [128][6]
    unsigned long long* ckey = (unsigned long long*)(aabb + NCH * 6);  // [128]
    float*    cbx = (float*)(ckey + NCH);                 // [128]
    float*    cby = cbx + NCH;
    float*    cbz = cby + NCH;

    __shared__ float    s_g[6];          // global aabb
    __shared__ float    s_w[FPS_W][6];
    __shared__ unsigned s_wsum[FPS_W], s_wbase[FPS_W];
    __shared__ float    s_cc[3];

    const int b    = blockIdx.x;
    const int tid  = threadIdx.x;
    const int lane = tid & 31, w = tid >> 5;
    const float* xb = xyz + (size_t)b * NN * 3;

    // ---- global AABB ----
    float mnx = 1e30f, mny = 1e30f, mnz = 1e30f;
    float mxx = -1e30f, mxy = -1e30f, mxz = -1e30f;
    for (int i = tid; i < NN; i += FPS_T) {
        const float x = xb[3 * i], y = xb[3 * i + 1], z = xb[3 * i + 2];
        mnx = fminf(mnx, x); mny = fminf(mny, y); mnz = fminf(mnz, z);
        mxx = fmaxf(mxx, x); mxy = fmaxf(mxy, y); mxz = fmaxf(mxz, z);
    }
#pragma unroll
    for (int off = 16; off; off >>= 1) {
        mnx = fminf(mnx, __shfl_xor_sync(0xffffffffu, mnx, off));
        mny = fminf(mny, __shfl_xor_sync(0xffffffffu, mny, off));
        mnz = fminf(mnz, __shfl_xor_sync(0xffffffffu, mnz, off));
        mxx = fmaxf(mxx, __shfl_xor_sync(0xffffffffu, mxx, off));
        mxy = fmaxf(mxy, __shfl_xor_sync(0xffffffffu, mxy, off));
        mxz = fmaxf(mxz, __shfl_xor_sync(0xffffffffu, mxz, off));
    }
    if (lane == 0) {
        s_w[w][0] = mnx; s_w[w][1] = mny; s_w[w][2] = mnz;
        s_w[w][3] = mxx; s_w[w][4] = mxy; s_w[w][5] = mxz;
    }
    // init hist + chunk keys while waiting
    for (int i = tid; i < NCELL; i += FPS_T) hist[i] = 0;
    for (int c = tid; c < NCH; c += FPS_T)
        ckey[c] = ((unsigned long long)__float_as_uint(1e10f)) << 14;
    __syncthreads();
    if (tid == 0) {
        float a0 = 1e30f, a1 = 1e30f, a2 = 1e30f, a3 = -1e30f, a4 = -1e30f, a5 = -1e30f;
        for (int i = 0; i < FPS_W; i++) {
            a0 = fminf(a0, s_w[i][0]); a1 = fminf(a1, s_w[i][1]); a2 = fminf(a2, s_w[i][2]);
            a3 = fmaxf(a3, s_w[i][3]); a4 = fmaxf(a4, s_w[i][4]); a5 = fmaxf(a5, s_w[i][5]);
        }
        s_g[0] = a0; s_g[1] = a1; s_g[2] = a2; s_g[3] = a3; s_g[4] = a4; s_g[5] = a5;
        // initial centroid = original point 0 (reference seeds far0 = 0)
        s_cc[0] = xb[0]; s_cc[1] = xb[1]; s_cc[2] = xb[2];
    }
    __syncthreads();

    const float gmnx = s_g[0], gmny = s_g[1], gmnz = s_g[2];
    const float isx = 16.f / fmaxf(s_g[3] - gmnx, 1e-9f);
    const float isy = 16.f / fmaxf(s_g[4] - gmny, 1e-9f);
    const float isz = 8.f  / fmaxf(s_g[5] - gmnz, 1e-9f);

    // ---- histogram ----
    for (int i = tid; i < NN; i += FPS_T) {
        const int c = fps_cell(xb[3 * i], xb[3 * i + 1], xb[3 * i + 2],
                               gmnx, gmny, gmnz, isx, isy, isz);
        atomicAdd(&hist[c], 1u);
    }
    __syncthreads();

    // ---- exclusive scan of hist[2048] ----
    {
        const int t4 = tid * 4;
        const unsigned v0 = hist[t4], v1 = hist[t4 + 1], v2 = hist[t4 + 2], v3 = hist[t4 + 3];
        const unsigned s = v0 + v1 + v2 + v3;
        unsigned inc = s;
#pragma unroll
        for (int off = 1; off < 32; off <<= 1) {
            const unsigned n = __shfl_up_sync(0xffffffffu, inc, off);
            if (lane >= off) inc += n;
        }
        if (lane == 31) s_wsum[w] = inc;
        __syncthreads();
        if (tid < FPS_W) {
            const unsigned ws = s_wsum[tid];
            unsigned winc = ws;
#pragma unroll
            for (int off = 1; off < FPS_W; off <<= 1) {
                const unsigned n = __shfl_up_sync(0x0000ffffu, winc, off);
                if ((int)tid >= off) winc += n;
            }
            s_wbase[tid] = winc - ws;
        }
        __syncthreads();
        const unsigned base = s_wbase[w] + (inc - s);
        hist[t4]     = base;
        hist[t4 + 1] = base + v0;
        hist[t4 + 2] = base + v0 + v1;
        hist[t4 + 3] = base + v0 + v1 + v2;
    }
    __syncthreads();

    // ---- scatter: perm[slot] = original index ----
    for (int i = tid; i < NN; i += FPS_T) {
        const int c = fps_cell(xb[3 * i], xb[3 * i + 1], xb[3 * i + 2],
                               gmnx, gmny, gmnz, isx, isy, isz);
        const unsigned slot = atomicAdd(&hist[c], 1u);
        perm[slot] = (unsigned)i;
    }
    __syncthreads();

    // ---- owner fill: coords + dist regs, chunk AABBs ----
    // warp w owns slots [1024w, 1024(w+1)); chunk q local: slots 1024w+128q+lane+32k
    float zr[32], dr[32];
    const int wbase = w * 1024;
#pragma unroll
    for (int q = 0; q < CHQ; q++) {
        float lmn0 = 1e30f, lmn1 = 1e30f, lmn2 = 1e30f;
        float lmx0 = -1e30f, lmx1 = -1e30f, lmx2 = -1e30f;
#pragma unroll
        for (int k = 0; k < 4; k++) {
            const int slot = wbase + q * 128 + lane + 32 * k;
            const unsigned pi = perm[slot];
            const float x = __ldg(xb + 3 * pi);
            const float y = __ldg(xb + 3 * pi + 1);
            const float z = __ldg(xb + 3 * pi + 2);
            sxy[slot] = make_float2(x, y);
            zr[q * 4 + k] = z;
            dr[q * 4 + k] = 1e10f;
            lmn0 = fminf(lmn0, x); lmn1 = fminf(lmn1, y); lmn2 = fminf(lmn2, z);
            lmx0 = fmaxf(lmx0, x); lmx1 = fmaxf(lmx1, y); lmx2 = fmaxf(lmx2, z);
        }
#pragma unroll
        for (int off = 16; off; off >>= 1) {
            lmn0 = fminf(lmn0, __shfl_xor_sync(0xffffffffu, lmn0, off));
            lmn1 = fminf(lmn1, __shfl_xor_sync(0xffffffffu, lmn1, off));
            lmn2 = fminf(lmn2, __shfl_xor_sync(0xffffffffu, lmn2, off));
            lmx0 = fmaxf(lmx0, __shfl_xor_sync(0xffffffffu, lmx0, off));
            lmx1 = fmaxf(lmx1, __shfl_xor_sync(0xffffffffu, lmx1, off));
            lmx2 = fmaxf(lmx2, __shfl_xor_sync(0xffffffffu, lmx2, off));
        }
        if (lane == 0) {
            const int c = w * CHQ + q;
            aabb[c * 6 + 0] = lmn0; aabb[c * 6 + 1] = lmn1; aabb[c * 6 + 2] = lmn2;
            aabb[c * 6 + 3] = lmx0; aabb[c * 6 + 4] = lmx1; aabb[c * 6 + 5] = lmx2;
        }
    }
    __syncthreads();

    float* outx = out_newxyz + (size_t)b * SS * 3;

    // ---- main FPS loop ----
    for (int j = 0; j < SS; j++) {
        const float ccx = s_cc[0], ccy = s_cc[1], ccz = s_cc[2];
        if (tid == 0) {
            outx[3 * j + 0] = ccx;
            outx[3 * j + 1] = ccy;
            outx[3 * j + 2] = ccz;
        }
        const float nccx = -ccx, nccy = -ccy, nccz = -ccz;

        // prune test: lanes 0..7 each test one of this warp's 8 chunks
        bool a = false;
        if (lane < CHQ) {
            const int c = w * CHQ + lane;
            const float* bb = aabb + c * 6;
            const float dxm = fmaxf(fmaxf(__fadd_rn(bb[0], nccx), -__fadd_rn(bb[3], nccx)), 0.f);
            const float dym = fmaxf(fmaxf(__fadd_rn(bb[1], nccy), -__fadd_rn(bb[4], nccy)), 0.f);
            const float dzm = fmaxf(fmaxf(__fadd_rn(bb[2], nccz), -__fadd_rn(bb[5], nccz)), 0.f);
            const float dmin2 = __fadd_rn(__fadd_rn(__fmul_rn(dxm, dxm), __fmul_rn(dym, dym)),
                                          __fmul_rn(dzm, dzm));
            const float cm = __uint_as_float((unsigned)(ckey[c] >> 14));
            a = dmin2 < cm;
        }
        const unsigned act = __ballot_sync(0xffffffffu, a);

#pragma unroll
        for (int q = 0; q < CHQ; q++) {
            if ((act >> q) & 1u) {
                const int c = w * CHQ + q;
                const int sb = wbase + q * 128 + lane;
                unsigned long long bk = 0ull;
                float bx = 0.f, by = 0.f, bz = 0.f;
#pragma unroll
                for (int k = 0; k < 4; k++) {
                    const int slot = sb + 32 * k;
                    const float2 xy = sxy[slot];
                    const float zz = zr[q * 4 + k];
                    const float dx = __fadd_rn(xy.x, nccx);
                    const float dy = __fadd_rn(xy.y, nccy);
                    const float dz = __fadd_rn(zz, nccz);
                    const float d = __fadd_rn(__fadd_rn(__fmul_rn(dx, dx), __fmul_rn(dy, dy)),
                                              __fmul_rn(dz, dz));
                    const float nd = fminf(dr[q * 4 + k], d);
                    dr[q * 4 + k] = nd;
                    const unsigned long long key =
                        ((unsigned long long)__float_as_uint(nd) << 14) |
                        (unsigned long long)(16383u - perm[slot]);
                    if (key > bk) { bk = key; bx = xy.x; by = xy.y; bz = zz; }
                }
                unsigned long long mk = bk;
#pragma unroll
                for (int off = 16; off; off >>= 1) {
                    const unsigned long long ok = __shfl_xor_sync(0xffffffffu, mk, off);
                    if (ok > mk) mk = ok;
                }
                const unsigned own = __ballot_sync(0xffffffffu, bk == mk);
                if (lane == (__ffs(own) - 1)) {
                    ckey[c] = mk; cbx[c] = bx; cby[c] = by; cbz[c] = bz;
                }
            }
        }
        __syncthreads();

        // global reduce over 128 chunk keys by warp 0
        if (w == 0) {
            unsigned long long K = 0ull;
            int ci = 0;
#pragma unroll
            for (int t2 = 0; t2 < 4; t2++) {
                const int c = lane + 32 * t2;
                const unsigned long long k2 = ckey[c];
                if (k2 > K) { K = k2; ci = c; }
            }
#pragma unroll
            for (int off = 16; off; off >>= 1) {
                const unsigned long long oK = __shfl_xor_sync(0xffffffffu, K, off);
                const int oc = __shfl_xor_sync(0xffffffffu, ci, off);
                if (oK > K) { K = oK; ci = oc; }
            }
            if (lane == 0) { s_cc[0] = cbx[ci]; s_cc[1] = cby[ci]; s_cc[2] = cbz[ci]; }
        }
        __syncthreads();
    }
}

// =================================================================
// Kernel 2: transpose features (B,C,N) -> (B,N,C)
// =================================================================
__global__ void transpose_kernel(const float* __restrict__ f)
{
    __shared__ float tile[32][33];
    const int b  = blockIdx.z;
    const int n0 = blockIdx.x * 32;
    const int c0 = blockIdx.y * 32;
    const int tx = threadIdx.x, ty = threadIdx.y;
    tile[ty][tx] = f[((size_t)b * CIN + (c0 + ty)) * NN + n0 + tx];
    __syncthreads();
    g_featsT[((size_t)b * NN + (n0 + ty)) * CIN + c0 + tx] = tile[tx][ty];
}

// =================================================================
// Kernel 3: ball query (one warp per group), first-32-ascending
// =================================================================
__global__ void ballq_kernel(const float* __restrict__ xyz,
                             const float* __restrict__ newxyz)
{
    const int g    = blockIdx.x * 8 + (threadIdx.x >> 5);
    const int lane = threadIdx.x & 31;
    const int b    = g >> 12;
    const float* xb = xyz + (size_t)b * NN * 3;

    const float cx = newxyz[g * 3 + 0];
    const float cy = newxyz[g * 3 + 1];
    const float cz = newxyz[g * 3 + 2];

    int* out = g_ballIdx + g * NSAMP;
    int cnt = 0;

    for (int base = 0; base < NN && cnt < NSAMP; base += 32) {
        const int i = base + lane;
        const float dx = xb[3 * i + 0] - cx;
        const float dy = xb[3 * i + 1] - cy;
        const float dz = xb[3 * i + 2] - cz;
        const float d2 = __fadd_rn(__fadd_rn(__fmul_rn(dx, dx), __fmul_rn(dy, dy)),
                                   __fmul_rn(dz, dz));
        const bool inb = d2 < 0.25f;  // radius^2 = 0.25 exactly
        const unsigned m = __ballot_sync(0xffffffffu, inb);
        const int pos = cnt + __popc(m & ((1u << lane) - 1u));
        if (inb && pos < NSAMP) out[pos] = i;
        cnt += __popc(m);
    }
    __syncwarp();
    if (cnt == 0) {
        out[lane] = 0;
    } else if (cnt < NSAMP) {
        const int first = out[0];
        if (lane >= cnt) out[lane] = first;
    }
    if (lane == 0) g_ballCnt[g] = cnt;
}

// =================================================================
// Kernel 4: fused gather + 3-layer MLP + maxpool + agg + score
// One block (256 threads) per group. Weight smem strides padded to
// odd (65/65/129) => conflict-free staging stores AND compute loads.
// =================================================================
#define W1_STR 65
#define W2_STR 65
#define W3_STR 129
#define SM_INT_F   (67 * 36)          // 2412 (div by 4)
#define SM_W1_F    4356               // 67*65 padded to mult of 4
#define SM_W2_F    (64 * W2_STR)      // 4160
#define SM_W3_F    (64 * W3_STR)      // 8256
#define SM_H_F     (64 * 36)          // 2304
#define MLP_SMEM_FLOATS (SM_INT_F + SM_W1_F + SM_W2_F + SM_W3_F + 2 * SM_H_F + 256 + 256 + 128 + 128 + 32)

__global__ __launch_bounds__(256, 2) void group_mlp_kernel(
    const float* __restrict__ xyz,
    const float* __restrict__ newxyz,
    const float* __restrict__ w1, const float* __restrict__ b1,
    const float* __restrict__ w2, const float* __restrict__ b2,
    const float* __restrict__ w3, const float* __restrict__ b3,
    const float* __restrict__ wa, const float* __restrict__ ba,
    const float* __restrict__ wc, const float* __restrict__ bc,
    float* __restrict__ d_out)
{
    extern __shared__ float sm[];
    float* inT     = sm;                    // [67][36]  input  (i-major, nb fast)
    float* w1s     = inT + SM_INT_F;        // [67][65]  (i-major, oc fast, padded)
    float* w2s     = w1s + SM_W1_F;         // [64][65]
    float* w3s     = w2s + SM_W2_F;         // [64][129]
    float* h1T     = w3s + SM_W3_F;         // [64][36]
    float* h2T     = h1T + SM_H_F;          // [64][36]
    float* bss     = h2T + SM_H_F;          // b1[64] b2[64] b3[128]
    float* poolbuf = bss + 256;             // [128][2]
    float* pooled  = poolbuf + 256;         // [128]
    float* aggv    = pooled + 128;          // [128]
    int*   idxs    = (int*)(aggv + 128);    // [32]

    const int g = blockIdx.x;
    const int b = g >> 12;
    const int s = g & 4095;
    const int tid = threadIdx.x;

    // ---- stage indices, biases, weights (transposed, padded strides) ----
    if (tid < 32)  idxs[tid] = g_ballIdx[g * NSAMP + tid];
    if (tid < 64)       bss[tid] = b1[tid];
    else if (tid < 128) bss[tid] = b2[tid - 64];
    if (tid < 128) bss[128 + tid] = b3[tid];

    for (int e = tid; e < 64 * 67; e += 256) {
        const int oc = e / 67, i = e % 67;
        w1s[i * W1_STR + oc] = w1[e];
    }
    for (int e = tid; e < 64 * 64; e += 256) {
        const int oc = e >> 6, i = e & 63;
        w2s[i * W2_STR + oc] = w2[e];
    }
    for (int e = tid; e < 128 * 64; e += 256) {
        const int oc = e >> 6, i = e & 63;
        w3s[i * W3_STR + oc] = w3[e];
    }
    __syncthreads();

    // ---- gather: inT[i][nb] = (i<3) ? xyz[idx]-center : featsT[idx][i-3] ----
    const float* xb = xyz + (size_t)b * NN * 3;
    const float cx = newxyz[g * 3 + 0];
    const float cy = newxyz[g * 3 + 1];
    const float cz = newxyz[g * 3 + 2];
    for (int e = tid; e < 32 * 67; e += 256) {
        const int nb = e & 31;
        const int i  = e >> 5;
        const int pi = idxs[nb];
        float v;
        if (i == 0)      v = xb[pi * 3 + 0] - cx;
        else if (i == 1) v = xb[pi * 3 + 1] - cy;
        else if (i == 2) v = xb[pi * 3 + 2] - cz;
        else             v = g_featsT[((size_t)b * NN + pi) * CIN + (i - 3)];
        inT[i * 36 + nb] = v;
    }
    __syncthreads();

    // ---- layer 1: 67 -> 64, ReLU ----
    {
        const int oc = tid & 63, ng = tid >> 6;  // 4 groups of 8 neighbors
        float acc[8];
        const float bv = bss[oc];
#pragma unroll
        for (int n = 0; n < 8; n++) acc[n] = bv;
        for (int i = 0; i < 67; i++) {
            const float w = w1s[i * W1_STR + oc];
            const float4* xp = (const float4*)(inT + i * 36 + ng * 8);
            const float4 x0 = xp[0], x1 = xp[1];
            acc[0] += w * x0.x; acc[1] += w * x0.y; acc[2] += w * x0.z; acc[3] += w * x0.w;
            acc[4] += w * x1.x; acc[5] += w * x1.y; acc[6] += w * x1.z; acc[7] += w * x1.w;
        }
        float* hp = h1T + oc * 36 + ng * 8;
#pragma unroll
        for (int n = 0; n < 8; n++) hp[n] = fmaxf(acc[n], 0.f);
    }
    __syncthreads();

    // ---- layer 2: 64 -> 64, ReLU ----
    {
        const int oc = tid & 63, ng = tid >> 6;
        float acc[8];
        const float bv = bss[64 + oc];
#pragma unroll
        for (int n = 0; n < 8; n++) acc[n] = bv;
        for (int i = 0; i < 64; i++) {
            const float w = w2s[i * W2_STR + oc];
            const float4* xp = (const float4*)(h1T + i * 36 + ng * 8);
            const float4 x0 = xp[0], x1 = xp[1];
            acc[0] += w * x0.x; acc[1] += w * x0.y; acc[2] += w * x0.z; acc[3] += w * x0.w;
            acc[4] += w * x1.x; acc[5] += w * x1.y; acc[6] += w * x1.z; acc[7] += w * x1.w;
        }
        float* hp = h2T + oc * 36 + ng * 8;
#pragma unroll
        for (int n = 0; n < 8; n++) hp[n] = fmaxf(acc[n], 0.f);
    }
    __syncthreads();

    // ---- layer 3: 64 -> 128, ReLU fused with local max over neighbors ----
    {
        const int oc = tid & 127, ng = tid >> 7;  // 2 groups of 16 neighbors
        float acc[16];
        const float bv = bss[128 + oc];
#pragma unroll
        for (int n = 0; n < 16; n++) acc[n] = bv;
        for (int i = 0; i < 64; i++) {
            const float w = w3s[i * W3_STR + oc];
            const float4* xp = (const float4*)(h2T + i * 36 + ng * 16);
            const float4 x0 = xp[0], x1 = xp[1], x2 = xp[2], x3 = xp[3];
            acc[0]  += w * x0.x; acc[1]  += w * x0.y; acc[2]  += w * x0.z; acc[3]  += w * x0.w;
            acc[4]  += w * x1.x; acc[5]  += w * x1.y; acc[6]  += w * x1.z; acc[7]  += w * x1.w;
            acc[8]  += w * x2.x; acc[9]  += w * x2.y; acc[10] += w * x2.z; acc[11] += w * x2.w;
            acc[12] += w * x3.x; acc[13] += w * x3.y; acc[14] += w * x3.z; acc[15] += w * x3.w;
        }
        float m = acc[0];
#pragma unroll
        for (int n = 1; n < 16; n++) m = fmaxf(m, acc[n]);
        m = fmaxf(m, 0.f);  // max(relu(x)) == relu(max(x))
        poolbuf[oc * 2 + ng] = m;
    }
    __syncthreads();

    const int cnt = g_ballCnt[g];
    if (tid < 128) {
        const float m = fmaxf(poolbuf[tid * 2], poolbuf[tid * 2 + 1]);
        pooled[tid] = (cnt > 0) ? m : 0.f;
    }
    __syncthreads();

    // ---- aggregation MLP: 128 -> 128, ReLU; write new_features ----
    if (tid < 128) {
        const int o = tid;
        float acc = ba[o];
        const float4* w4 = (const float4*)(wa + o * 128);
#pragma unroll 8
        for (int i = 0; i < 32; i++) {
            const float4 wv = __ldg(w4 + i);
            acc += pooled[4 * i + 0] * wv.x;
            acc += pooled[4 * i + 1] * wv.y;
            acc += pooled[4 * i + 2] * wv.z;
            acc += pooled[4 * i + 3] * wv.w;
        }
        const float a = fmaxf(acc, 0.f);
        aggv[o] = a;
        d_out[OUT_FEAT_OFF + ((size_t)(b * 128 + o)) * SS + s] = a;
    }
    __syncthreads();

    // ---- confidence score: wc . agg + bc ----
    if (tid < 32) {
        float p = 0.f;
#pragma unroll
        for (int k = 0; k < 4; k++) {
            const int i = k * 32 + tid;
            p += aggv[i] * wc[i];
        }
#pragma unroll
        for (int off = 16; off; off >>= 1)
            p += __shfl_down_sync(0xffffffffu, p, off);
        if (tid == 0)
            d_out[OUT_SCORE_OFF + b * SS + s] = p + bc[0];
    }
}

// =================================================================
// launch
// =================================================================
extern "C" void kernel_launch(void* const* d_in, const int* in_sizes, int n_in,
                              void* d_out, int out_size)
{
    const float* xyz      = (const float*)d_in[0];
    const float* features = (const float*)d_in[1];
    const float* w1 = (const float*)d_in[2];
    const float* b1 = (const float*)d_in[3];
    const float* w2 = (const float*)d_in[4];
    const float* b2 = (const float*)d_in[5];
    const float* w3 = (const float*)d_in[6];
    const float* b3 = (const float*)d_in[7];
    const float* wa = (const float*)d_in[8];
    const float* ba = (const float*)d_in[9];
    const float* wc = (const float*)d_in[10];
    const float* bc = (const float*)d_in[11];
    float* out = (float*)d_out;

    static bool attr_set = false;
    if (!attr_set) {
        cudaFuncSetAttribute(fps_kernel, cudaFuncAttributeMaxDynamicSharedMemorySize,
                             FPS_SMEM_BYTES);
        cudaFuncSetAttribute(group_mlp_kernel, cudaFuncAttributeMaxDynamicSharedMemorySize,
                             MLP_SMEM_FLOATS * (int)sizeof(float));
        attr_set = true;
    }

    // 1) FPS -> writes new_xyz into d_out[0:24576)
    fps_kernel<<<BB, FPS_T, FPS_SMEM_BYTES>>>(xyz, out + OUT_XYZ_OFF);

    // 2) transpose features to (B,N,C)
    transpose_kernel<<<dim3(NN / 32, CIN / 32, BB), dim3(32, 32)>>>(features);

    // 3) ball query
    ballq_kernel<<<(BB * SS) / 8, 256>>>(xyz, out + OUT_XYZ_OFF);

    // 4) fused gather + MLP + pool + agg + score
    group_mlp_kernel<<<BB * SS, 256, MLP_SMEM_FLOATS * sizeof(float)>>>(
        xyz, out + OUT_XYZ_OFF,
        w1, b1, w2, b2, w3, b3, wa, ba, wc, bc, out);
}

// round 4
// speedup vs baseline: 1.1816x; 1.1202x over previous
#include <cuda_runtime.h>
#include <cuda_bf16.h>

// Problem constants
#define BB 2
#define NN 16384
#define CIN 64
#define SS 4096
#define NSAMP 32

// Output layout (floats): new_xyz | new_features | scores
#define OUT_XYZ_OFF   0
#define OUT_FEAT_OFF  (BB * SS * 3)                       // 24576
#define OUT_SCORE_OFF (OUT_FEAT_OFF + BB * 128 * SS)      // 1073152

// ---------------- scratch (no allocations allowed) ----------------
__device__ float g_featsT[BB * NN * CIN];    // (B,N,C) transposed features, 8 MB
__device__ int   g_ballIdx[BB * SS * NSAMP]; // neighbor indices
__device__ int   g_ballCnt[BB * SS];         // in-ball counts (0 => empty)

// =================================================================
// Kernel 1: FPS, hot/cold split + Morton chunk pruning.
//  - "hot" = largest-r2 tail points (<=768), scanned EVERY iteration
//    (these poison chunk AABBs otherwise). Deterministic threshold.
//  - "cold" = rest, Morton-sorted into <=128 chunks of 128 w/ AABBs;
//    chunk rescanned only if dmin2(centroid, box) < chunk cached max.
//  - all per-point arithmetic bit-identical to reference:
//    ((dx^2+dy^2)+dz^2) in RN, fminf; argmax via u64 key
//    (dist_bits<<14)|(16383-origIdx) => exact first-index ties.
// =================================================================
#define FPS_T   512
#define HOTCAP  1024
#define HOT_TGT 768
#define NCELL   2048
#define NCHMAX  128

// dynamic smem: cxy float2[16384] 131072 | cperm u16[16384] 32768 |
// hot4 float4[1024] 16384 | hist u32[2048] 8192 | aabb f32[128*6] 3072 |
// ckey u64[128] 1024 | cwin float4[128] 2048   => 194560 B
#define FPS_SMEM_BYTES (131072 + 32768 + 16384 + 8192 + 3072 + 1024 + 2048)

__device__ __forceinline__ float r2_rn(float x, float y, float z)
{
    return __fadd_rn(__fadd_rn(__fmul_rn(x, x), __fmul_rn(y, y)), __fmul_rn(z, z));
}
__device__ __forceinline__ float dist_rn(float x, float y, float z,
                                         float nx, float ny, float nz)
{
    const float dx = __fadd_rn(x, nx);
    const float dy = __fadd_rn(y, ny);
    const float dz = __fadd_rn(z, nz);
    return __fadd_rn(__fadd_rn(__fmul_rn(dx, dx), __fmul_rn(dy, dy)), __fmul_rn(dz, dz));
}

__device__ __forceinline__ int fps_cell(float x, float y, float z,
                                        float mnx, float mny, float mnz,
                                        float isx, float isy, float isz)
{
    int qx = __float2int_rd((x - mnx) * isx); qx = max(0, min(15, qx));
    int qy = __float2int_rd((y - mny) * isy); qy = max(0, min(15, qy));
    int qz = __float2int_rd((z - mnz) * isz); qz = max(0, min(7,  qz));
    return  (qx & 1)        | ((qy & 1) << 1)        | ((qz & 1) << 2)
         | (((qx >> 1) & 1) << 3) | (((qy >> 1) & 1) << 4) | (((qz >> 1) & 1) << 5)
         | (((qx >> 2) & 1) << 6) | (((qy >> 2) & 1) << 7) | (((qz >> 2) & 1) << 8)
         | (((qx >> 3) & 1) << 9) | (((qy >> 3) & 1) << 10);
}

__global__ __launch_bounds__(FPS_T) void fps_kernel(
    const float* __restrict__ xyz, float* __restrict__ out_newxyz)
{
    extern __shared__ unsigned char raw[];
    float2*         cxy   = (float2*)raw;                          // [16384]
    unsigned short* cperm = (unsigned short*)(cxy + NN);           // [16384]
    float4*         hot4  = (float4*)(cperm + NN);                 // [1024]
    unsigned*       hist  = (unsigned*)(hot4 + HOTCAP);            // [2048]
    float*          aabb  = (float*)(hist + NCELL);                // [128*6]
    unsigned long long* ckey = (unsigned long long*)(aabb + NCHMAX * 6); // [128]
    float4*         cwin  = (float4*)(ckey + NCHMAX);              // [128]

    __shared__ unsigned long long s_wk[16];
    __shared__ float s_wx[16], s_wy[16], s_wz[16];
    __shared__ float s_cc[3];
    __shared__ float s_wred[16][6];
    __shared__ unsigned s_wsum[16], s_wbase[16];
    __shared__ unsigned s_rh[128];
    __shared__ float s_r2b, s_thresh;
    __shared__ float s_grid[6];   // gmnx,gmny,gmnz,isx,isy,isz
    __shared__ unsigned s_hotCnt;

    const int b    = blockIdx.x;
    const int tid  = threadIdx.x;
    const int lane = tid & 31, w = tid >> 5;
    const float* xb = xyz + (size_t)b * NN * 3;

    // ---- pass 0: global AABB ----
    {
        float mnx = 1e30f, mny = 1e30f, mnz = 1e30f;
        float mxx = -1e30f, mxy = -1e30f, mxz = -1e30f;
        for (int i = tid; i < NN; i += FPS_T) {
            const float x = xb[3 * i], y = xb[3 * i + 1], z = xb[3 * i + 2];
            mnx = fminf(mnx, x); mny = fminf(mny, y); mnz = fminf(mnz, z);
            mxx = fmaxf(mxx, x); mxy = fmaxf(mxy, y); mxz = fmaxf(mxz, z);
        }
#pragma unroll
        for (int off = 16; off; off >>= 1) {
            mnx = fminf(mnx, __shfl_xor_sync(0xffffffffu, mnx, off));
            mny = fminf(mny, __shfl_xor_sync(0xffffffffu, mny, off));
            mnz = fminf(mnz, __shfl_xor_sync(0xffffffffu, mnz, off));
            mxx = fmaxf(mxx, __shfl_xor_sync(0xffffffffu, mxx, off));
            mxy = fmaxf(mxy, __shfl_xor_sync(0xffffffffu, mxy, off));
            mxz = fmaxf(mxz, __shfl_xor_sync(0xffffffffu, mxz, off));
        }
        if (lane == 0) {
            s_wred[w][0] = mnx; s_wred[w][1] = mny; s_wred[w][2] = mnz;
            s_wred[w][3] = mxx; s_wred[w][4] = mxy; s_wred[w][5] = mxz;
        }
    }
    for (int i = tid; i < NCELL; i += FPS_T) hist[i] = 0;
    if (tid < 128) { s_rh[tid] = 0; ckey[tid] = 0ull; }
    if (tid == 0) s_hotCnt = 0;
    __syncthreads();
    if (tid == 0) {
        float a0 = 1e30f, a1 = 1e30f, a2 = 1e30f, a3 = -1e30f, a4 = -1e30f, a5 = -1e30f;
        for (int i = 0; i < 16; i++) {
            a0 = fminf(a0, s_wred[i][0]); a1 = fminf(a1, s_wred[i][1]); a2 = fminf(a2, s_wred[i][2]);
            a3 = fmaxf(a3, s_wred[i][3]); a4 = fmaxf(a4, s_wred[i][4]); a5 = fmaxf(a5, s_wred[i][5]);
        }
        s_grid[0] = a0; s_grid[1] = a1; s_grid[2] = a2;
        s_grid[3] = 16.f / fmaxf(a3 - a0, 1e-9f);
        s_grid[4] = 16.f / fmaxf(a4 - a1, 1e-9f);
        s_grid[5] = 8.f  / fmaxf(a5 - a2, 1e-9f);
        const float bx = fmaxf(fabsf(a0), fabsf(a3));
        const float by = fmaxf(fabsf(a1), fabsf(a4));
        const float bz = fmaxf(fabsf(a2), fabsf(a5));
        s_r2b = bx * bx + by * by + bz * bz + 1e-6f;
        s_cc[0] = xb[0]; s_cc[1] = xb[1]; s_cc[2] = xb[2];
    }
    __syncthreads();

    const float gmnx = s_grid[0], gmny = s_grid[1], gmnz = s_grid[2];
    const float isx = s_grid[3], isy = s_grid[4], isz = s_grid[5];
    const float r2b = s_r2b;

    // ---- pass 1: r2 histogram (128 bins) ----
    for (int i = tid; i < NN; i += FPS_T) {
        const float r2 = r2_rn(xb[3 * i], xb[3 * i + 1], xb[3 * i + 2]);
        const int bin = min(127, (int)(r2 * (128.f / r2b)));
        atomicAdd(&s_rh[bin], 1u);
    }
    __syncthreads();
    if (tid == 0) {
        unsigned acc = 0;
        float thr = 3e38f;  // default: nothing hot
        for (int bb2 = 127; bb2 >= 0; bb2--) {
            if (acc + s_rh[bb2] > HOT_TGT) break;
            acc += s_rh[bb2];
            thr = (float)bb2 * (r2b / 128.f);
        }
        s_thresh = thr;
    }
    __syncthreads();
    const float thresh = s_thresh;

    // ---- pass 2: Morton histogram over cold ----
    for (int i = tid; i < NN; i += FPS_T) {
        const float x = xb[3 * i], y = xb[3 * i + 1], z = xb[3 * i + 2];
        if (r2_rn(x, y, z) < thresh) {
            const int c = fps_cell(x, y, z, gmnx, gmny, gmnz, isx, isy, isz);
            atomicAdd(&hist[c], 1u);
        }
    }
    __syncthreads();

    // ---- exclusive scan of hist[2048] ----
    {
        const int t4 = tid * 4;
        const unsigned v0 = hist[t4], v1 = hist[t4 + 1], v2 = hist[t4 + 2], v3 = hist[t4 + 3];
        const unsigned s = v0 + v1 + v2 + v3;
        unsigned inc = s;
#pragma unroll
        for (int off = 1; off < 32; off <<= 1) {
            const unsigned n = __shfl_up_sync(0xffffffffu, inc, off);
            if (lane >= off) inc += n;
        }
        if (lane == 31) s_wsum[w] = inc;
        __syncthreads();
        if (tid < 16) {
            const unsigned ws = s_wsum[tid];
            unsigned winc = ws;
#pragma unroll
            for (int off = 1; off < 16; off <<= 1) {
                const unsigned n = __shfl_up_sync(0x0000ffffu, winc, off);
                if ((int)tid >= off) winc += n;
            }
            s_wbase[tid] = winc - ws;
        }
        __syncthreads();
        const unsigned base = s_wbase[w] + (inc - s);
        hist[t4]     = base;
        hist[t4 + 1] = base + v0;
        hist[t4 + 2] = base + v0 + v1;
        hist[t4 + 3] = base + v0 + v1 + v2;
    }
    __syncthreads();

    // ---- pass 3: scatter hot / cold ----
    for (int i = tid; i < NN; i += FPS_T) {
        const float x = xb[3 * i], y = xb[3 * i + 1], z = xb[3 * i + 2];
        if (r2_rn(x, y, z) >= thresh) {
            const unsigned pos = atomicAdd(&s_hotCnt, 1u);
            hot4[pos] = make_float4(x, y, z, __uint_as_float((unsigned)i));
        } else {
            const int c = fps_cell(x, y, z, gmnx, gmny, gmnz, isx, isy, isz);
            const unsigned slot = atomicAdd(&hist[c], 1u);
            cxy[slot] = make_float2(x, y);
            cperm[slot] = (unsigned short)i;
        }
    }
    __syncthreads();

    const int hc    = (int)s_hotCnt;          // deterministic (threshold-based)
    const int coldN = NN - hc;
    const int nch   = (coldN + 127) >> 7;

    // pads
    for (int s2 = hc + tid; s2 < HOTCAP; s2 += FPS_T)
        hot4[s2] = (hc > 0) ? hot4[0]
                            : make_float4(xb[0], xb[1], xb[2], __uint_as_float(0u));
    for (int s2 = coldN + tid; s2 < nch * 128; s2 += FPS_T) {
        cxy[s2]   = cxy[coldN - 1];
        cperm[s2] = cperm[coldN - 1];
    }
    __syncthreads();

    // ---- owner fill: z+dist regs, chunk AABBs ----
    float cz[32], cd[32], hd[2];
#pragma unroll
    for (int k = 0; k < 32; k++) { cz[k] = 0.f; cd[k] = 1e10f; }
    hd[0] = hd[1] = 1e10f;
#pragma unroll
    for (int m = 0; m < 8; m++) {
        const int c = w + 16 * m;
        if (c < nch) {
            float lmn0 = 1e30f, lmn1 = 1e30f, lmn2 = 1e30f;
            float lmx0 = -1e30f, lmx1 = -1e30f, lmx2 = -1e30f;
#pragma unroll
            for (int k = 0; k < 4; k++) {
                const int slot = c * 128 + lane + 32 * k;
                const float2 xy = cxy[slot];
                const float z = __ldg(xb + 3 * (int)cperm[slot] + 2);
                cz[m * 4 + k] = z;
                lmn0 = fminf(lmn0, xy.x); lmn1 = fminf(lmn1, xy.y); lmn2 = fminf(lmn2, z);
                lmx0 = fmaxf(lmx0, xy.x); lmx1 = fmaxf(lmx1, xy.y); lmx2 = fmaxf(lmx2, z);
            }
#pragma unroll
            for (int off = 16; off; off >>= 1) {
                lmn0 = fminf(lmn0, __shfl_xor_sync(0xffffffffu, lmn0, off));
                lmn1 = fminf(lmn1, __shfl_xor_sync(0xffffffffu, lmn1, off));
                lmn2 = fminf(lmn2, __shfl_xor_sync(0xffffffffu, lmn2, off));
                lmx0 = fmaxf(lmx0, __shfl_xor_sync(0xffffffffu, lmx0, off));
                lmx1 = fmaxf(lmx1, __shfl_xor_sync(0xffffffffu, lmx1, off));
                lmx2 = fmaxf(lmx2, __shfl_xor_sync(0xffffffffu, lmx2, off));
            }
            if (lane == 0) {
                aabb[c * 6 + 0] = lmn0; aabb[c * 6 + 1] = lmn1; aabb[c * 6 + 2] = lmn2;
                aabb[c * 6 + 3] = lmx0; aabb[c * 6 + 4] = lmx1; aabb[c * 6 + 5] = lmx2;
                ckey[c] = ((unsigned long long)__float_as_uint(1e10f)) << 14;
                cwin[c] = make_float4(0.f, 0.f, 0.f, 0.f);
            }
        }
    }
    __syncthreads();

    float* outx = out_newxyz + (size_t)b * SS * 3;

    // ---- main loop ----
    for (int j = 0; j < SS; j++) {
        const float ccx = s_cc[0], ccy = s_cc[1], ccz = s_cc[2];
        if (tid == 0) {
            outx[3 * j + 0] = ccx;
            outx[3 * j + 1] = ccy;
            outx[3 * j + 2] = ccz;
        }
        const float nx = -ccx, ny = -ccy, nz = -ccz;

        // hot scan (2 slots/thread, always)
        unsigned long long hk = 0ull;
        float hx = 0.f, hy = 0.f, hz = 0.f;
#pragma unroll
        for (int k = 0; k < 2; k++) {
            const float4 h = hot4[tid + FPS_T * k];
            const float d = dist_rn(h.x, h.y, h.z, nx, ny, nz);
            const float nd = fminf(hd[k], d);
            hd[k] = nd;
            const unsigned long long key =
                ((unsigned long long)__float_as_uint(nd) << 14) |
                (unsigned long long)(16383u - __float_as_uint(h.w));
            if (key > hk) { hk = key; hx = h.x; hy = h.y; hz = h.z; }
        }

        // prune (lanes 0..7 test this warp's chunks)
        bool act = false;
        if (lane < 8) {
            const int c = w + 16 * lane;
            if (c < nch) {
                const float* bb2 = aabb + c * 6;
                const float dxm = fmaxf(fmaxf(__fadd_rn(bb2[0], nx), -__fadd_rn(bb2[3], nx)), 0.f);
                const float dym = fmaxf(fmaxf(__fadd_rn(bb2[1], ny), -__fadd_rn(bb2[4], ny)), 0.f);
                const float dzm = fmaxf(fmaxf(__fadd_rn(bb2[2], nz), -__fadd_rn(bb2[5], nz)), 0.f);
                const float dmin2 = __fadd_rn(__fadd_rn(__fmul_rn(dxm, dxm), __fmul_rn(dym, dym)),
                                              __fmul_rn(dzm, dzm));
                const float cm = __uint_as_float((unsigned)(ckey[c] >> 14));
                act = dmin2 < cm;
            }
        }
        const unsigned mask = __ballot_sync(0xffffffffu, act);

#pragma unroll
        for (int m = 0; m < 8; m++) {
            if ((mask >> m) & 1u) {   // warp-uniform branch
                const int c = w + 16 * m;
                unsigned long long bk = 0ull;
                float bx = 0.f, by = 0.f, bz = 0.f;
#pragma unroll
                for (int k = 0; k < 4; k++) {
                    const int slot = c * 128 + lane + 32 * k;
                    const float2 xy = cxy[slot];
                    const float zz = cz[m * 4 + k];
                    const float d = dist_rn(xy.x, xy.y, zz, nx, ny, nz);
                    const float nd = fminf(cd[m * 4 + k], d);
                    cd[m * 4 + k] = nd;
                    const unsigned long long key =
                        ((unsigned long long)__float_as_uint(nd) << 14) |
                        (unsigned long long)(16383u - (unsigned)cperm[slot]);
                    if (key > bk) { bk = key; bx = xy.x; by = xy.y; bz = zz; }
                }
                unsigned long long mk = bk;
#pragma unroll
                for (int off = 16; off; off >>= 1) {
                    const unsigned long long ok = __shfl_xor_sync(0xffffffffu, mk, off);
                    if (ok > mk) mk = ok;
                }
                const unsigned own = __ballot_sync(0xffffffffu, bk == mk);
                if (lane == (__ffs(own) - 1)) {
                    ckey[c] = mk;
                    cwin[c] = make_float4(bx, by, bz, 0.f);
                }
            }
        }
        __syncwarp();

        // combine: hot best + this warp's 8 chunk keys -> warp key
        unsigned long long K = hk;
        float kx = hx, ky = hy, kz = hz;
        if (lane < 8) {
            const int c = w + 16 * lane;
            if (c < nch) {
                const unsigned long long ck = ckey[c];
                if (ck > K) {
                    const float4 cw = cwin[c];
                    K = ck; kx = cw.x; ky = cw.y; kz = cw.z;
                }
            }
        }
#pragma unroll
        for (int off = 16; off; off >>= 1) {
            const unsigned long long oK = __shfl_xor_sync(0xffffffffu, K, off);
            const float ox = __shfl_xor_sync(0xffffffffu, kx, off);
            const float oy = __shfl_xor_sync(0xffffffffu, ky, off);
            const float oz = __shfl_xor_sync(0xffffffffu, kz, off);
            if (oK > K) { K = oK; kx = ox; ky = oy; kz = oz; }
        }
        if (lane == 0) { s_wk[w] = K; s_wx[w] = kx; s_wy[w] = ky; s_wz[w] = kz; }
        __syncthreads();

        if (w == 0) {
            unsigned long long K2 = 0ull;
            float k2x = 0.f, k2y = 0.f, k2z = 0.f;
            if (lane < 16) { K2 = s_wk[lane]; k2x = s_wx[lane]; k2y = s_wy[lane]; k2z = s_wz[lane]; }
#pragma unroll
            for (int off = 8; off; off >>= 1) {
                const unsigned long long oK = __shfl_xor_sync(0xffffffffu, K2, off);
                const float ox = __shfl_xor_sync(0xffffffffu, k2x, off);
                const float oy = __shfl_xor_sync(0xffffffffu, k2y, off);
                const float oz = __shfl_xor_sync(0xffffffffu, k2z, off);
                if (oK > K2) { K2 = oK; k2x = ox; k2y = oy; k2z = oz; }
            }
            if (lane == 0) { s_cc[0] = k2x; s_cc[1] = k2y; s_cc[2] = k2z; }
        }
        __syncthreads();
    }
}

// =================================================================
// Kernel 2: transpose features (B,C,N) -> (B,N,C)
// =================================================================
__global__ void transpose_kernel(const float* __restrict__ f)
{
    __shared__ float tile[32][33];
    const int b  = blockIdx.z;
    const int n0 = blockIdx.x * 32;
    const int c0 = blockIdx.y * 32;
    const int tx = threadIdx.x, ty = threadIdx.y;
    tile[ty][tx] = f[((size_t)b * CIN + (c0 + ty)) * NN + n0 + tx];
    __syncthreads();
    g_featsT[((size_t)b * NN + (n0 + ty)) * CIN + c0 + tx] = tile[tx][ty];
}

// =================================================================
// Kernel 3: ball query (one warp per group), first-32-ascending
// =================================================================
__global__ void ballq_kernel(const float* __restrict__ xyz,
                             const float* __restrict__ newxyz)
{
    const int g    = blockIdx.x * 8 + (threadIdx.x >> 5);
    const int lane = threadIdx.x & 31;
    const int b    = g >> 12;
    const float* xb = xyz + (size_t)b * NN * 3;

    const float cx = newxyz[g * 3 + 0];
    const float cy = newxyz[g * 3 + 1];
    const float cz = newxyz[g * 3 + 2];

    int* out = g_ballIdx + g * NSAMP;
    int cnt = 0;

    for (int base = 0; base < NN && cnt < NSAMP; base += 32) {
        const int i = base + lane;
        const float dx = xb[3 * i + 0] - cx;
        const float dy = xb[3 * i + 1] - cy;
        const float dz = xb[3 * i + 2] - cz;
        const float d2 = __fadd_rn(__fadd_rn(__fmul_rn(dx, dx), __fmul_rn(dy, dy)),
                                   __fmul_rn(dz, dz));
        const bool inb = d2 < 0.25f;  // radius^2 = 0.25 exactly
        const unsigned m = __ballot_sync(0xffffffffu, inb);
        const int pos = cnt + __popc(m & ((1u << lane) - 1u));
        if (inb && pos < NSAMP) out[pos] = i;
        cnt += __popc(m);
    }
    __syncwarp();
    if (cnt == 0) {
        out[lane] = 0;
    } else if (cnt < NSAMP) {
        const int first = out[0];
        if (lane >= cnt) out[lane] = first;
    }
    if (lane == 0) g_ballCnt[g] = cnt;
}

// =================================================================
// Kernel 4: fused gather + 3-layer MLP + maxpool + agg + score
// One block (256 threads) per group. Weight smem strides padded to
// odd (65/65/129) => conflict-free staging stores AND compute loads.
// =================================================================
#define W1_STR 65
#define W2_STR 65
#define W3_STR 129
#define SM_INT_F   (67 * 36)
#define SM_W1_F    4356
#define SM_W2_F    (64 * W2_STR)
#define SM_W3_F    (64 * W3_STR)
#define SM_H_F     (64 * 36)
#define MLP_SMEM_FLOATS (SM_INT_F + SM_W1_F + SM_W2_F + SM_W3_F + 2 * SM_H_F + 256 + 256 + 128 + 128 + 32)

__global__ __launch_bounds__(256, 2) void group_mlp_kernel(
    const float* __restrict__ xyz,
    const float* __restrict__ newxyz,
    const float* __restrict__ w1, const float* __restrict__ b1,
    const float* __restrict__ w2, const float* __restrict__ b2,
    const float* __restrict__ w3, const float* __restrict__ b3,
    const float* __restrict__ wa, const float* __restrict__ ba,
    const float* __restrict__ wc, const float* __restrict__ bc,
    float* __restrict__ d_out)
{
    extern __shared__ float sm[];
    float* inT     = sm;
    float* w1s     = inT + SM_INT_F;
    float* w2s     = w1s + SM_W1_F;
    float* w3s     = w2s + SM_W2_F;
    float* h1T     = w3s + SM_W3_F;
    float* h2T     = h1T + SM_H_F;
    float* bss     = h2T + SM_H_F;
    float* poolbuf = bss + 256;
    float* pooled  = poolbuf + 256;
    float* aggv    = pooled + 128;
    int*   idxs    = (int*)(aggv + 128);

    const int g = blockIdx.x;
    const int b = g >> 12;
    const int s = g & 4095;
    const int tid = threadIdx.x;

    if (tid < 32)  idxs[tid] = g_ballIdx[g * NSAMP + tid];
    if (tid < 64)       bss[tid] = b1[tid];
    else if (tid < 128) bss[tid] = b2[tid - 64];
    if (tid < 128) bss[128 + tid] = b3[tid];

    for (int e = tid; e < 64 * 67; e += 256) {
        const int oc = e / 67, i = e % 67;
        w1s[i * W1_STR + oc] = w1[e];
    }
    for (int e = tid; e < 64 * 64; e += 256) {
        const int oc = e >> 6, i = e & 63;
        w2s[i * W2_STR + oc] = w2[e];
    }
    for (int e = tid; e < 128 * 64; e += 256) {
        const int oc = e >> 6, i = e & 63;
        w3s[i * W3_STR + oc] = w3[e];
    }
    __syncthreads();

    const float* xb = xyz + (size_t)b * NN * 3;
    const float cx = newxyz[g * 3 + 0];
    const float cy = newxyz[g * 3 + 1];
    const float cz = newxyz[g * 3 + 2];
    for (int e = tid; e < 32 * 67; e += 256) {
        const int nb = e & 31;
        const int i  = e >> 5;
        const int pi = idxs[nb];
        float v;
        if (i == 0)      v = xb[pi * 3 + 0] - cx;
        else if (i == 1) v = xb[pi * 3 + 1] - cy;
        else if (i == 2) v = xb[pi * 3 + 2] - cz;
        else             v = g_featsT[((size_t)b * NN + pi) * CIN + (i - 3)];
        inT[i * 36 + nb] = v;
    }
    __syncthreads();

    {
        const int oc = tid & 63, ng = tid >> 6;
        float acc[8];
        const float bv = bss[oc];
#pragma unroll
        for (int n = 0; n < 8; n++) acc[n] = bv;
        for (int i = 0; i < 67; i++) {
            const float w = w1s[i * W1_STR + oc];
            const float4* xp = (const float4*)(inT + i * 36 + ng * 8);
            const float4 x0 = xp[0], x1 = xp[1];
            acc[0] += w * x0.x; acc[1] += w * x0.y; acc[2] += w * x0.z; acc[3] += w * x0.w;
            acc[4] += w * x1.x; acc[5] += w * x1.y; acc[6] += w * x1.z; acc[7] += w * x1.w;
        }
        float* hp = h1T + oc * 36 + ng * 8;
#pragma unroll
        for (int n = 0; n < 8; n++) hp[n] = fmaxf(acc[n], 0.f);
    }
    __syncthreads();

    {
        const int oc = tid & 63, ng = tid >> 6;
        float acc[8];
        const float bv = bss[64 + oc];
#pragma unroll
        for (int n = 0; n < 8; n++) acc[n] = bv;
        for (int i = 0; i < 64; i++) {
            const float w = w2s[i * W2_STR + oc];
            const float4* xp = (const float4*)(h1T + i * 36 + ng * 8);
            const float4 x0 = xp[0], x1 = xp[1];
            acc[0] += w * x0.x; acc[1] += w * x0.y; acc[2] += w * x0.z; acc[3] += w * x0.w;
            acc[4] += w * x1.x; acc[5] += w * x1.y; acc[6] += w * x1.z; acc[7] += w * x1.w;
        }
        float* hp = h2T + oc * 36 + ng * 8;
#pragma unroll
        for (int n = 0; n < 8; n++) hp[n] = fmaxf(acc[n], 0.f);
    }
    __syncthreads();

    {
        const int oc = tid & 127, ng = tid >> 7;
        float acc[16];
        const float bv = bss[128 + oc];
#pragma unroll
        for (int n = 0; n < 16; n++) acc[n] = bv;
        for (int i = 0; i < 64; i++) {
            const float w = w3s[i * W3_STR + oc];
            const float4* xp = (const float4*)(h2T + i * 36 + ng * 16);
            const float4 x0 = xp[0], x1 = xp[1], x2 = xp[2], x3 = xp[3];
            acc[0]  += w * x0.x; acc[1]  += w * x0.y; acc[2]  += w * x0.z; acc[3]  += w * x0.w;
            acc[4]  += w * x1.x; acc[5]  += w * x1.y; acc[6]  += w * x1.z; acc[7]  += w * x1.w;
            acc[8]  += w * x2.x; acc[9]  += w * x2.y; acc[10] += w * x2.z; acc[11] += w * x2.w;
            acc[12] += w * x3.x; acc[13] += w * x3.y; acc[14] += w * x3.z; acc[15] += w * x3.w;
        }
        float m = acc[0];
#pragma unroll
        for (int n = 1; n < 16; n++) m = fmaxf(m, acc[n]);
        m = fmaxf(m, 0.f);
        poolbuf[oc * 2 + ng] = m;
    }
    __syncthreads();

    const int cnt = g_ballCnt[g];
    if (tid < 128) {
        const float m = fmaxf(poolbuf[tid * 2], poolbuf[tid * 2 + 1]);
        pooled[tid] = (cnt > 0) ? m : 0.f;
    }
    __syncthreads();

    if (tid < 128) {
        const int o = tid;
        float acc = ba[o];
        const float4* w4 = (const float4*)(wa + o * 128);
#pragma unroll 8
        for (int i = 0; i < 32; i++) {
            const float4 wv = __ldg(w4 + i);
            acc += pooled[4 * i + 0] * wv.x;
            acc += pooled[4 * i + 1] * wv.y;
            acc += pooled[4 * i + 2] * wv.z;
            acc += pooled[4 * i + 3] * wv.w;
        }
        const float a = fmaxf(acc, 0.f);
        aggv[o] = a;
        d_out[OUT_FEAT_OFF + ((size_t)(b * 128 + o)) * SS + s] = a;
    }
    __syncthreads();

    if (tid < 32) {
        float p = 0.f;
#pragma unroll
        for (int k = 0; k < 4; k++) {
            const int i = k * 32 + tid;
            p += aggv[i] * wc[i];
        }
#pragma unroll
        for (int off = 16; off; off >>= 1)
            p += __shfl_down_sync(0xffffffffu, p, off);
        if (tid == 0)
            d_out[OUT_SCORE_OFF + b * SS + s] = p + bc[0];
    }
}

// =================================================================
// launch
// =================================================================
extern "C" void kernel_launch(void* const* d_in, const int* in_sizes, int n_in,
                              void* d_out, int out_size)
{
    const float* xyz      = (const float*)d_in[0];
    const float* features = (const float*)d_in[1];
    const float* w1 = (const float*)d_in[2];
    const float* b1 = (const float*)d_in[3];
    const float* w2 = (const float*)d_in[4];
    const float* b2 = (const float*)d_in[5];
    const float* w3 = (const float*)d_in[6];
    const float* b3 = (const float*)d_in[7];
    const float* wa = (const float*)d_in[8];
    const float* ba = (const float*)d_in[9];
    const float* wc = (const float*)d_in[10];
    const float* bc = (const float*)d_in[11];
    float* out = (float*)d_out;

    static bool attr_set = false;
    if (!attr_set) {
        cudaFuncSetAttribute(fps_kernel, cudaFuncAttributeMaxDynamicSharedMemorySize,
                             FPS_SMEM_BYTES);
        cudaFuncSetAttribute(group_mlp_kernel, cudaFuncAttributeMaxDynamicSharedMemorySize,
                             MLP_SMEM_FLOATS * (int)sizeof(float));
        attr_set = true;
    }

    // 1) FPS -> writes new_xyz into d_out[0:24576)
    fps_kernel<<<BB, FPS_T, FPS_SMEM_BYTES>>>(xyz, out + OUT_XYZ_OFF);

    // 2) transpose features to (B,N,C)
    transpose_kernel<<<dim3(NN / 32, CIN / 32, BB), dim3(32, 32)>>>(features);

    // 3) ball query
    ballq_kernel<<<(BB * SS) / 8, 256>>>(xyz, out + OUT_XYZ_OFF);

    // 4) fused gather + MLP + pool + agg + score
    group_mlp_kernel<<<BB * SS, 256, MLP_SMEM_FLOATS * sizeof(float)>>>(
        xyz, out + OUT_XYZ_OFF,
        w1, b1, w2, b2, w3, b3, wa, ba, wc, bc, out);
}

// round 5
// speedup vs baseline: 1.1850x; 1.0029x over previous
#include <cuda_runtime.h>
#include <cuda_bf16.h>

// Problem constants
#define BB 2
#define NN 16384
#define CIN 64
#define SS 4096
#define NSAMP 32

// Output layout (floats): new_xyz | new_features | scores
#define OUT_XYZ_OFF   0
#define OUT_FEAT_OFF  (BB * SS * 3)                       // 24576
#define OUT_SCORE_OFF (OUT_FEAT_OFF + BB * 128 * SS)      // 1073152

// ---------------- scratch (no allocations allowed) ----------------
__device__ float g_featsT[BB * NN * CIN];    // (B,N,C) transposed features, 8 MB
__device__ int   g_ballIdx[BB * SS * NSAMP]; // neighbor indices
__device__ int   g_ballCnt[BB * SS];         // in-ball counts (0 => empty)

typedef unsigned long long u64;

// =================================================================
// Kernel 1: FPS, hot/cold split + Morton chunk pruning, 256 threads.
//  - hot (<=~768 far points, padded to 1024): scanned every iter
//  - cold: Morton-sorted into <=128 chunks of 128 pts, AABB pruned
//  - per-point math bit-identical to reference; argmax key
//    (dist_bits<<14)|(16383-idx) => exact first-index tie-break
//  - reduces carry (u64 key, u32 src); coords read once from
//    cwin[src] / hot4[src-128] after the cross-warp reduce
// =================================================================
#define FPS_T   256
#define FPS_W   8
#define CW      16      // chunks per warp
#define HOTCAP  1024
#define HOT_TGT 768
#define NCELL   2048
#define NCHMAX  128

// dyn smem: cxy f2[16384]=131072 | inv16 u16[16384]=32768 | hot4 f4[1024]=16384
//         | hist u32[2048]=8192 | aabb f32[768]=3072 | ckey u64[128]=1024
//         | cwin f4[128]=2048    => 194560 B
#define FPS_SMEM_BYTES (131072 + 32768 + 16384 + 8192 + 3072 + 1024 + 2048)

__device__ __forceinline__ float r2_rn(float x, float y, float z)
{
    return __fadd_rn(__fadd_rn(__fmul_rn(x, x), __fmul_rn(y, y)), __fmul_rn(z, z));
}
__device__ __forceinline__ float dist_rn(float x, float y, float z,
                                         float nx, float ny, float nz)
{
    const float dx = __fadd_rn(x, nx);
    const float dy = __fadd_rn(y, ny);
    const float dz = __fadd_rn(z, nz);
    return __fadd_rn(__fadd_rn(__fmul_rn(dx, dx), __fmul_rn(dy, dy)), __fmul_rn(dz, dz));
}

__device__ __forceinline__ int fps_cell(float x, float y, float z,
                                        float mnx, float mny, float mnz,
                                        float isx, float isy, float isz)
{
    int qx = __float2int_rd((x - mnx) * isx); qx = max(0, min(15, qx));
    int qy = __float2int_rd((y - mny) * isy); qy = max(0, min(15, qy));
    int qz = __float2int_rd((z - mnz) * isz); qz = max(0, min(7,  qz));
    return  (qx & 1)        | ((qy & 1) << 1)        | ((qz & 1) << 2)
         | (((qx >> 1) & 1) << 3) | (((qy >> 1) & 1) << 4) | (((qz >> 1) & 1) << 5)
         | (((qx >> 2) & 1) << 6) | (((qy >> 2) & 1) << 7) | (((qz >> 2) & 1) << 8)
         | (((qx >> 3) & 1) << 9) | (((qy >> 3) & 1) << 10);
}

__global__ __launch_bounds__(FPS_T) void fps_kernel(
    const float* __restrict__ xyz, float* __restrict__ out_newxyz)
{
    extern __shared__ unsigned char raw[];
    float2*         cxy   = (float2*)raw;                      // [16384]
    unsigned short* inv16 = (unsigned short*)(cxy + NN);       // [16384]
    float4*         hot4  = (float4*)(inv16 + NN);             // [1024]
    unsigned*       hist  = (unsigned*)(hot4 + HOTCAP);        // [2048]
    float*          aabb  = (float*)(hist + NCELL);            // [128*6]
    u64*            ckey  = (u64*)(aabb + NCHMAX * 6);         // [128]
    float4*         cwin  = (float4*)(ckey + NCHMAX);          // [128]

    __shared__ u64      s_wk[FPS_W];
    __shared__ unsigned s_ws[FPS_W];
    __shared__ float    s_wred[FPS_W][6];
    __shared__ unsigned s_wsum[FPS_W], s_wbase[FPS_W];
    __shared__ unsigned s_rh[128];
    __shared__ float    s_r2b, s_thresh;
    __shared__ float    s_grid[6];
    __shared__ unsigned s_hotCnt;

    const int b    = blockIdx.x;
    const int tid  = threadIdx.x;
    const int lane = tid & 31, w = tid >> 5;
    const float* xb = xyz + (size_t)b * NN * 3;

    // ---- pass 0: global AABB ----
    {
        float mnx = 1e30f, mny = 1e30f, mnz = 1e30f;
        float mxx = -1e30f, mxy = -1e30f, mxz = -1e30f;
        for (int i = tid; i < NN; i += FPS_T) {
            const float x = xb[3 * i], y = xb[3 * i + 1], z = xb[3 * i + 2];
            mnx = fminf(mnx, x); mny = fminf(mny, y); mnz = fminf(mnz, z);
            mxx = fmaxf(mxx, x); mxy = fmaxf(mxy, y); mxz = fmaxf(mxz, z);
        }
#pragma unroll
        for (int off = 16; off; off >>= 1) {
            mnx = fminf(mnx, __shfl_xor_sync(0xffffffffu, mnx, off));
            mny = fminf(mny, __shfl_xor_sync(0xffffffffu, mny, off));
            mnz = fminf(mnz, __shfl_xor_sync(0xffffffffu, mnz, off));
            mxx = fmaxf(mxx, __shfl_xor_sync(0xffffffffu, mxx, off));
            mxy = fmaxf(mxy, __shfl_xor_sync(0xffffffffu, mxy, off));
            mxz = fmaxf(mxz, __shfl_xor_sync(0xffffffffu, mxz, off));
        }
        if (lane == 0) {
            s_wred[w][0] = mnx; s_wred[w][1] = mny; s_wred[w][2] = mnz;
            s_wred[w][3] = mxx; s_wred[w][4] = mxy; s_wred[w][5] = mxz;
        }
    }
    for (int i = tid; i < NCELL; i += FPS_T) hist[i] = 0;
    if (tid < 128) { s_rh[tid] = 0; ckey[tid] = 0ull; }
    if (tid == 0) s_hotCnt = 0;
    __syncthreads();
    if (tid == 0) {
        float a0 = 1e30f, a1 = 1e30f, a2 = 1e30f, a3 = -1e30f, a4 = -1e30f, a5 = -1e30f;
        for (int i = 0; i < FPS_W; i++) {
            a0 = fminf(a0, s_wred[i][0]); a1 = fminf(a1, s_wred[i][1]); a2 = fminf(a2, s_wred[i][2]);
            a3 = fmaxf(a3, s_wred[i][3]); a4 = fmaxf(a4, s_wred[i][4]); a5 = fmaxf(a5, s_wred[i][5]);
        }
        s_grid[0] = a0; s_grid[1] = a1; s_grid[2] = a2;
        s_grid[3] = 16.f / fmaxf(a3 - a0, 1e-9f);
        s_grid[4] = 16.f / fmaxf(a4 - a1, 1e-9f);
        s_grid[5] = 8.f  / fmaxf(a5 - a2, 1e-9f);
        const float bx = fmaxf(fabsf(a0), fabsf(a3));
        const float by = fmaxf(fabsf(a1), fabsf(a4));
        const float bz = fmaxf(fabsf(a2), fabsf(a5));
        s_r2b = bx * bx + by * by + bz * bz + 1e-6f;
    }
    __syncthreads();

    const float gmnx = s_grid[0], gmny = s_grid[1], gmnz = s_grid[2];
    const float isx = s_grid[3], isy = s_grid[4], isz = s_grid[5];
    const float r2b = s_r2b;

    // ---- pass 1: r2 histogram ----
    for (int i = tid; i < NN; i += FPS_T) {
        const float r2 = r2_rn(xb[3 * i], xb[3 * i + 1], xb[3 * i + 2]);
        const int bin = min(127, (int)(r2 * (128.f / r2b)));
        atomicAdd(&s_rh[bin], 1u);
    }
    __syncthreads();
    if (tid == 0) {
        unsigned acc = 0;
        float thr = 3e38f;
        for (int q = 127; q >= 0; q--) {
            if (acc + s_rh[q] > HOT_TGT) break;
            acc += s_rh[q];
            thr = (float)q * (r2b / 128.f);
        }
        s_thresh = thr;
    }
    __syncthreads();
    const float thresh = s_thresh;

    // ---- pass 2: Morton histogram over cold ----
    for (int i = tid; i < NN; i += FPS_T) {
        const float x = xb[3 * i], y = xb[3 * i + 1], z = xb[3 * i + 2];
        if (r2_rn(x, y, z) < thresh) {
            const int c = fps_cell(x, y, z, gmnx, gmny, gmnz, isx, isy, isz);
            atomicAdd(&hist[c], 1u);
        }
    }
    __syncthreads();

    // ---- exclusive scan of hist[2048] (8 per thread) ----
    {
        const int t8 = tid * 8;
        unsigned v[8], s = 0;
#pragma unroll
        for (int q = 0; q < 8; q++) { v[q] = hist[t8 + q]; s += v[q]; }
        unsigned inc = s;
#pragma unroll
        for (int off = 1; off < 32; off <<= 1) {
            const unsigned n = __shfl_up_sync(0xffffffffu, inc, off);
            if (lane >= off) inc += n;
        }
        if (lane == 31) s_wsum[w] = inc;
        __syncthreads();
        if (tid < FPS_W) {
            const unsigned ws = s_wsum[tid];
            unsigned winc = ws;
#pragma unroll
            for (int off = 1; off < FPS_W; off <<= 1) {
                const unsigned n = __shfl_up_sync(0x000000ffu, winc, off);
                if ((int)tid >= off) winc += n;
            }
            s_wbase[tid] = winc - ws;
        }
        __syncthreads();
        unsigned run = s_wbase[w] + (inc - s);
#pragma unroll
        for (int q = 0; q < 8; q++) { hist[t8 + q] = run; run += v[q]; }
    }
    __syncthreads();

    // ---- pass 3: scatter hot / cold (inv16 = 16383 - i) ----
    for (int i = tid; i < NN; i += FPS_T) {
        const float x = xb[3 * i], y = xb[3 * i + 1], z = xb[3 * i + 2];
        if (r2_rn(x, y, z) >= thresh) {
            const unsigned pos = atomicAdd(&s_hotCnt, 1u);
            hot4[pos] = make_float4(x, y, z, __uint_as_float(16383u - (unsigned)i));
        } else {
            const int c = fps_cell(x, y, z, gmnx, gmny, gmnz, isx, isy, isz);
            const unsigned slot = atomicAdd(&hist[c], 1u);
            cxy[slot]   = make_float2(x, y);
            inv16[slot] = (unsigned short)(16383u - (unsigned)i);
        }
    }
    __syncthreads();

    const int hc    = (int)s_hotCnt;
    const int coldN = NN - hc;
    const int nch   = (coldN + 127) >> 7;

    // pads
    for (int s2 = hc + tid; s2 < HOTCAP; s2 += FPS_T)
        hot4[s2] = (hc > 0) ? hot4[0]
                            : make_float4(xb[0], xb[1], xb[2], __uint_as_float(16383u));
    for (int s2 = coldN + tid; s2 < nch * 128; s2 += FPS_T) {
        cxy[s2]   = cxy[coldN - 1];
        inv16[s2] = inv16[coldN - 1];
    }
    __syncthreads();

    // ---- owner fill: z + dist regs, chunk AABBs ----
    float cz[64], cd[64], hd[4];
#pragma unroll
    for (int k = 0; k < 64; k++) { cz[k] = 0.f; cd[k] = 1e10f; }
#pragma unroll
    for (int k = 0; k < 4; k++) hd[k] = 1e10f;

#pragma unroll
    for (int m = 0; m < CW; m++) {
        const int c = w + FPS_W * m;
        if (c < nch) {
            float lmn0 = 1e30f, lmn1 = 1e30f, lmn2 = 1e30f;
            float lmx0 = -1e30f, lmx1 = -1e30f, lmx2 = -1e30f;
#pragma unroll
            for (int k = 0; k < 4; k++) {
                const int slot = c * 128 + lane + 32 * k;
                const float2 xy = cxy[slot];
                const int oi = 16383 - (int)inv16[slot];
                const float z = __ldg(xb + 3 * oi + 2);
                cz[m * 4 + k] = z;
                lmn0 = fminf(lmn0, xy.x); lmn1 = fminf(lmn1, xy.y); lmn2 = fminf(lmn2, z);
                lmx0 = fmaxf(lmx0, xy.x); lmx1 = fmaxf(lmx1, xy.y); lmx2 = fmaxf(lmx2, z);
            }
#pragma unroll
            for (int off = 16; off; off >>= 1) {
                lmn0 = fminf(lmn0, __shfl_xor_sync(0xffffffffu, lmn0, off));
                lmn1 = fminf(lmn1, __shfl_xor_sync(0xffffffffu, lmn1, off));
                lmn2 = fminf(lmn2, __shfl_xor_sync(0xffffffffu, lmn2, off));
                lmx0 = fmaxf(lmx0, __shfl_xor_sync(0xffffffffu, lmx0, off));
                lmx1 = fmaxf(lmx1, __shfl_xor_sync(0xffffffffu, lmx1, off));
                lmx2 = fmaxf(lmx2, __shfl_xor_sync(0xffffffffu, lmx2, off));
            }
            if (lane == 0) {
                aabb[c * 6 + 0] = lmn0; aabb[c * 6 + 1] = lmn1; aabb[c * 6 + 2] = lmn2;
                aabb[c * 6 + 3] = lmx0; aabb[c * 6 + 4] = lmx1; aabb[c * 6 + 5] = lmx2;
                ckey[c] = ((u64)__float_as_uint(1e10f)) << 14;  // forces first-iter scan
                cwin[c] = make_float4(0.f, 0.f, 0.f, 0.f);
            }
        }
    }
    __syncthreads();

    float* outx = out_newxyz + (size_t)b * SS * 3;
    float ccx = __ldg(xb + 0), ccy = __ldg(xb + 1), ccz = __ldg(xb + 2);

    // ---- main loop ----
    for (int j = 0; j < SS; j++) {
        if (tid == 0) {
            outx[3 * j + 0] = ccx;
            outx[3 * j + 1] = ccy;
            outx[3 * j + 2] = ccz;
        }
        const float nx = -ccx, ny = -ccy, nz = -ccz;

        // hot scan: 4 pts/thread, always
        u64 bK = 0ull; unsigned bS = 0u;
#pragma unroll
        for (int k = 0; k < 4; k++) {
            const int slot = tid + FPS_T * k;
            const float4 h = hot4[slot];
            const float d = dist_rn(h.x, h.y, h.z, nx, ny, nz);
            const float nd = fminf(hd[k], d);
            hd[k] = nd;
            const u64 key = ((u64)__float_as_uint(nd) << 14) | (u64)__float_as_uint(h.w);
            if (key > bK) { bK = key; bS = 128u + (unsigned)slot; }
        }

        // prune: lanes 0..15 test this warp's 16 chunks
        bool act = false;
        if (lane < CW) {
            const int c = w + FPS_W * lane;
            const float* bb2 = aabb + c * 6;
            const float dxm = fmaxf(fmaxf(__fadd_rn(bb2[0], nx), -__fadd_rn(bb2[3], nx)), 0.f);
            const float dym = fmaxf(fmaxf(__fadd_rn(bb2[1], ny), -__fadd_rn(bb2[4], ny)), 0.f);
            const float dzm = fmaxf(fmaxf(__fadd_rn(bb2[2], nz), -__fadd_rn(bb2[5], nz)), 0.f);
            const float dmin2 = __fadd_rn(__fadd_rn(__fmul_rn(dxm, dxm), __fmul_rn(dym, dym)),
                                          __fmul_rn(dzm, dzm));
            const float cm = __uint_as_float((unsigned)(ckey[c] >> 14));
            act = dmin2 < cm;   // ckey==0 for c>=nch => never active
        }
        const unsigned mask = __ballot_sync(0xffffffffu, act);

#pragma unroll
        for (int m = 0; m < CW; m++) {
            if ((mask >> m) & 1u) {   // warp-uniform
                const int c = w + FPS_W * m;
                u64 bk = 0ull;
                float bx = 0.f, by = 0.f, bz = 0.f;
#pragma unroll
                for (int k = 0; k < 4; k++) {
                    const int slot = c * 128 + lane + 32 * k;
                    const float2 xy = cxy[slot];
                    const float zz = cz[m * 4 + k];
                    const float d = dist_rn(xy.x, xy.y, zz, nx, ny, nz);
                    const float nd = fminf(cd[m * 4 + k], d);
                    cd[m * 4 + k] = nd;
                    const u64 key = ((u64)__float_as_uint(nd) << 14) | (u64)inv16[slot];
                    if (key > bk) { bk = key; bx = xy.x; by = xy.y; bz = zz; }
                }
                u64 mk = bk;
#pragma unroll
                for (int off = 16; off; off >>= 1) {
                    const u64 ok = __shfl_xor_sync(0xffffffffu, mk, off);
                    if (ok > mk) mk = ok;
                }
                const unsigned own = __ballot_sync(0xffffffffu, bk == mk);
                if (lane == (__ffs(own) - 1)) {
                    ckey[c] = mk;
                    cwin[c] = make_float4(bx, by, bz, 0.f);
                }
            }
        }

        // combine: own 16 chunk keys + hot best -> warp (key, src)
        if (lane < CW) {
            const int c = w + FPS_W * lane;
            const u64 ck = ckey[c];
            if (ck > bK) { bK = ck; bS = (unsigned)c; }
        }
#pragma unroll
        for (int off = 16; off; off >>= 1) {
            const u64 oK = __shfl_xor_sync(0xffffffffu, bK, off);
            const unsigned oS = __shfl_xor_sync(0xffffffffu, bS, off);
            if (oK > bK) { bK = oK; bS = oS; }
        }
        if (lane == 0) { s_wk[w] = bK; s_ws[w] = bS; }
        __syncthreads();

        // redundant cross-warp reduce (all warps, same result)
        u64 K = 0ull; unsigned S2 = 0u;
        if (lane < FPS_W) { K = s_wk[lane]; S2 = s_ws[lane]; }
#pragma unroll
        for (int off = 4; off; off >>= 1) {
            const u64 oK = __shfl_xor_sync(0xffffffffu, K, off);
            const unsigned oS = __shfl_xor_sync(0xffffffffu, S2, off);
            if (oK > K) { K = oK; S2 = oS; }
        }
        S2 = __shfl_sync(0xffffffffu, S2, 0);
        const float4 wv = (S2 < 128u) ? cwin[S2] : hot4[S2 - 128u];
        ccx = wv.x; ccy = wv.y; ccz = wv.z;
        __syncthreads();   // close WAR window on cwin / s_wk
    }
}

// =================================================================
// Kernel 2: transpose features (B,C,N) -> (B,N,C)
// =================================================================
__global__ void transpose_kernel(const float* __restrict__ f)
{
    __shared__ float tile[32][33];
    const int b  = blockIdx.z;
    const int n0 = blockIdx.x * 32;
    const int c0 = blockIdx.y * 32;
    const int tx = threadIdx.x, ty = threadIdx.y;
    tile[ty][tx] = f[((size_t)b * CIN + (c0 + ty)) * NN + n0 + tx];
    __syncthreads();
    g_featsT[((size_t)b * NN + (n0 + ty)) * CIN + c0 + tx] = tile[tx][ty];
}

// =================================================================
// Kernel 3: ball query (one warp per group), first-32-ascending
// =================================================================
__global__ void ballq_kernel(const float* __restrict__ xyz,
                             const float* __restrict__ newxyz)
{
    const int g    = blockIdx.x * 8 + (threadIdx.x >> 5);
    const int lane = threadIdx.x & 31;
    const int b    = g >> 12;
    const float* xb = xyz + (size_t)b * NN * 3;

    const float cx = newxyz[g * 3 + 0];
    const float cy = newxyz[g * 3 + 1];
    const float cz = newxyz[g * 3 + 2];

    int* out = g_ballIdx + g * NSAMP;
    int cnt = 0;

    for (int base = 0; base < NN && cnt < NSAMP; base += 32) {
        const int i = base + lane;
        const float dx = xb[3 * i + 0] - cx;
        const float dy = xb[3 * i + 1] - cy;
        const float dz = xb[3 * i + 2] - cz;
        const float d2 = __fadd_rn(__fadd_rn(__fmul_rn(dx, dx), __fmul_rn(dy, dy)),
                                   __fmul_rn(dz, dz));
        const bool inb = d2 < 0.25f;
        const unsigned m = __ballot_sync(0xffffffffu, inb);
        const int pos = cnt + __popc(m & ((1u << lane) - 1u));
        if (inb && pos < NSAMP) out[pos] = i;
        cnt += __popc(m);
    }
    __syncwarp();
    if (cnt == 0) {
        out[lane] = 0;
    } else if (cnt < NSAMP) {
        const int first = out[0];
        if (lane >= cnt) out[lane] = first;
    }
    if (lane == 0) g_ballCnt[g] = cnt;
}

// =================================================================
// Kernel 4: fused gather + 3-layer MLP + maxpool + agg + score
// =================================================================
#define W1_STR 65
#define W2_STR 65
#define W3_STR 129
#define SM_INT_F   (67 * 36)
#define SM_W1_F    4356
#define SM_W2_F    (64 * W2_STR)
#define SM_W3_F    (64 * W3_STR)
#define SM_H_F     (64 * 36)
#define MLP_SMEM_FLOATS (SM_INT_F + SM_W1_F + SM_W2_F + SM_W3_F + 2 * SM_H_F + 256 + 256 + 128 + 128 + 32)

__global__ __launch_bounds__(256, 2) void group_mlp_kernel(
    const float* __restrict__ xyz,
    const float* __restrict__ newxyz,
    const float* __restrict__ w1, const float* __restrict__ b1,
    const float* __restrict__ w2, const float* __restrict__ b2,
    const float* __restrict__ w3, const float* __restrict__ b3,
    const float* __restrict__ wa, const float* __restrict__ ba,
    const float* __restrict__ wc, const float* __restrict__ bc,
    float* __restrict__ d_out)
{
    extern __shared__ float sm[];
    float* inT     = sm;
    float* w1s     = inT + SM_INT_F;
    float* w2s     = w1s + SM_W1_F;
    float* w3s     = w2s + SM_W2_F;
    float* h1T     = w3s + SM_W3_F;
    float* h2T     = h1T + SM_H_F;
    float* bss     = h2T + SM_H_F;
    float* poolbuf = bss + 256;
    float* pooled  = poolbuf + 256;
    float* aggv    = pooled + 128;
    int*   idxs    = (int*)(aggv + 128);

    const int g = blockIdx.x;
    const int b = g >> 12;
    const int s = g & 4095;
    const int tid = threadIdx.x;

    if (tid < 32)  idxs[tid] = g_ballIdx[g * NSAMP + tid];
    if (tid < 64)       bss[tid] = b1[tid];
    else if (tid < 128) bss[tid] = b2[tid - 64];
    if (tid < 128) bss[128 + tid] = b3[tid];

    for (int e = tid; e < 64 * 67; e += 256) {
        const int oc = e / 67, i = e % 67;
        w1s[i * W1_STR + oc] = w1[e];
    }
    for (int e = tid; e < 64 * 64; e += 256) {
        const int oc = e >> 6, i = e & 63;
        w2s[i * W2_STR + oc] = w2[e];
    }
    for (int e = tid; e < 128 * 64; e += 256) {
        const int oc = e >> 6, i = e & 63;
        w3s[i * W3_STR + oc] = w3[e];
    }
    __syncthreads();

    const float* xb = xyz + (size_t)b * NN * 3;
    const float cx = newxyz[g * 3 + 0];
    const float cy = newxyz[g * 3 + 1];
    const float cz = newxyz[g * 3 + 2];
    for (int e = tid; e < 32 * 67; e += 256) {
        const int nb = e & 31;
        const int i  = e >> 5;
        const int pi = idxs[nb];
        float v;
        if (i == 0)      v = xb[pi * 3 + 0] - cx;
        else if (i == 1) v = xb[pi * 3 + 1] - cy;
        else if (i == 2) v = xb[pi * 3 + 2] - cz;
        else             v = g_featsT[((size_t)b * NN + pi) * CIN + (i - 3)];
        inT[i * 36 + nb] = v;
    }
    __syncthreads();

    {
        const int oc = tid & 63, ng = tid >> 6;
        float acc[8];
        const float bv = bss[oc];
#pragma unroll
        for (int n = 0; n < 8; n++) acc[n] = bv;
        for (int i = 0; i < 67; i++) {
            const float w = w1s[i * W1_STR + oc];
            const float4* xp = (const float4*)(inT + i * 36 + ng * 8);
            const float4 x0 = xp[0], x1 = xp[1];
            acc[0] += w * x0.x; acc[1] += w * x0.y; acc[2] += w * x0.z; acc[3] += w * x0.w;
            acc[4] += w * x1.x; acc[5] += w * x1.y; acc[6] += w * x1.z; acc[7] += w * x1.w;
        }
        float* hp = h1T + oc * 36 + ng * 8;
#pragma unroll
        for (int n = 0; n < 8; n++) hp[n] = fmaxf(acc[n], 0.f);
    }
    __syncthreads();

    {
        const int oc = tid & 63, ng = tid >> 6;
        float acc[8];
        const float bv = bss[64 + oc];
#pragma unroll
        for (int n = 0; n < 8; n++) acc[n] = bv;
        for (int i = 0; i < 64; i++) {
            const float w = w2s[i * W2_STR + oc];
            const float4* xp = (const float4*)(h1T + i * 36 + ng * 8);
            const float4 x0 = xp[0], x1 = xp[1];
            acc[0] += w * x0.x; acc[1] += w * x0.y; acc[2] += w * x0.z; acc[3] += w * x0.w;
            acc[4] += w * x1.x; acc[5] += w * x1.y; acc[6] += w * x1.z; acc[7] += w * x1.w;
        }
        float* hp = h2T + oc * 36 + ng * 8;
#pragma unroll
        for (int n = 0; n < 8; n++) hp[n] = fmaxf(acc[n], 0.f);
    }
    __syncthreads();

    {
        const int oc = tid & 127, ng = tid >> 7;
        float acc[16];
        const float bv = bss[128 + oc];
#pragma unroll
        for (int n = 0; n < 16; n++) acc[n] = bv;
        for (int i = 0; i < 64; i++) {
            const float w = w3s[i * W3_STR + oc];
            const float4* xp = (const float4*)(h2T + i * 36 + ng * 16);
            const float4 x0 = xp[0], x1 = xp[1], x2 = xp[2], x3 = xp[3];
            acc[0]  += w * x0.x; acc[1]  += w * x0.y; acc[2]  += w * x0.z; acc[3]  += w * x0.w;
            acc[4]  += w * x1.x; acc[5]  += w * x1.y; acc[6]  += w * x1.z; acc[7]  += w * x1.w;
            acc[8]  += w * x2.x; acc[9]  += w * x2.y; acc[10] += w * x2.z; acc[11] += w * x2.w;
            acc[12] += w * x3.x; acc[13] += w * x3.y; acc[14] += w * x3.z; acc[15] += w * x3.w;
        }
        float m = acc[0];
#pragma unroll
        for (int n = 1; n < 16; n++) m = fmaxf(m, acc[n]);
        m = fmaxf(m, 0.f);
        poolbuf[oc * 2 + ng] = m;
    }
    __syncthreads();

    const int cnt = g_ballCnt[g];
    if (tid < 128) {
        const float m = fmaxf(poolbuf[tid * 2], poolbuf[tid * 2 + 1]);
        pooled[tid] = (cnt > 0) ? m : 0.f;
    }
    __syncthreads();

    if (tid < 128) {
        const int o = tid;
        float acc = ba[o];
        const float4* w4 = (const float4*)(wa + o * 128);
#pragma unroll 8
        for (int i = 0; i < 32; i++) {
            const float4 wv = __ldg(w4 + i);
            acc += pooled[4 * i + 0] * wv.x;
            acc += pooled[4 * i + 1] * wv.y;
            acc += pooled[4 * i + 2] * wv.z;
            acc += pooled[4 * i + 3] * wv.w;
        }
        const float a = fmaxf(acc, 0.f);
        aggv[o] = a;
        d_out[OUT_FEAT_OFF + ((size_t)(b * 128 + o)) * SS + s] = a;
    }
    __syncthreads();

    if (tid < 32) {
        float p = 0.f;
#pragma unroll
        for (int k = 0; k < 4; k++) {
            const int i = k * 32 + tid;
            p += aggv[i] * wc[i];
        }
#pragma unroll
        for (int off = 16; off; off >>= 1)
            p += __shfl_down_sync(0xffffffffu, p, off);
        if (tid == 0)
            d_out[OUT_SCORE_OFF + b * SS + s] = p + bc[0];
    }
}

// =================================================================
// launch (transpose first so ncu -s window lands on fps_kernel)
// =================================================================
extern "C" void kernel_launch(void* const* d_in, const int* in_sizes, int n_in,
                              void* d_out, int out_size)
{
    const float* xyz      = (const float*)d_in[0];
    const float* features = (const float*)d_in[1];
    const float* w1 = (const float*)d_in[2];
    const float* b1 = (const float*)d_in[3];
    const float* w2 = (const float*)d_in[4];
    const float* b2 = (const float*)d_in[5];
    const float* w3 = (const float*)d_in[6];
    const float* b3 = (const float*)d_in[7];
    const float* wa = (const float*)d_in[8];
    const float* ba = (const float*)d_in[9];
    const float* wc = (const float*)d_in[10];
    const float* bc = (const float*)d_in[11];
    float* out = (float*)d_out;

    static bool attr_set = false;
    if (!attr_set) {
        cudaFuncSetAttribute(fps_kernel, cudaFuncAttributeMaxDynamicSharedMemorySize,
                             FPS_SMEM_BYTES);
        cudaFuncSetAttribute(group_mlp_kernel, cudaFuncAttributeMaxDynamicSharedMemorySize,
                             MLP_SMEM_FLOATS * (int)sizeof(float));
        attr_set = true;
    }

    // 1) transpose features to (B,N,C)  (independent of FPS)
    transpose_kernel<<<dim3(NN / 32, CIN / 32, BB), dim3(32, 32)>>>(features);

    // 2) FPS -> writes new_xyz into d_out[0:24576)
    fps_kernel<<<BB, FPS_T, FPS_SMEM_BYTES>>>(xyz, out + OUT_XYZ_OFF);

    // 3) ball query
    ballq_kernel<<<(BB * SS) / 8, 256>>>(xyz, out + OUT_XYZ_OFF);

    // 4) fused gather + MLP + pool + agg + score
    group_mlp_kernel<<<BB * SS, 256, MLP_SMEM_FLOATS * sizeof(float)>>>(
        xyz, out + OUT_XYZ_OFF,
        w1, b1, w2, b2, w3, b3, wa, ba, wc, bc, out);
}